// round 10
// baseline (speedup 1.0000x reference)
#include <cuda_runtime.h>
#include <cuda_bf16.h>
#include <cuda_fp16.h>
#include <math.h>
#include <stdint.h>

// ---------------- problem constants ----------------
#define BATCH 2
#define TT    1024
#define CC    768
#define HH    12
#define DD    64
#define LL    12
#define MROWS (BATCH*TT)      // 2048
#define C3    (3*CC)          // 2304
#define C4    (4*CC)          // 3072
#define VP    50304

// ---------------- scratch (device globals) ----------
__device__ float g_x  [MROWS*CC];
__device__ float g_qkv[MROWS*C3];

__device__ __half g_ln [MROWS*CC];
__device__ __half g_att[MROWS*CC];
__device__ __half g_act[MROWS*C4];

__device__ __half g_qkvw_h [(size_t)LL*C3*CC], g_qkvw_l [(size_t)LL*C3*CC];
__device__ __half g_projw_h[(size_t)LL*CC*CC], g_projw_l[(size_t)LL*CC*CC];
__device__ __half g_fcw_h  [(size_t)LL*C4*CC], g_fcw_l  [(size_t)LL*C4*CC];
__device__ __half g_fcpw_h [(size_t)LL*CC*C4], g_fcpw_l [(size_t)LL*CC*C4];
__device__ __half g_wte_h  [(size_t)VP*CC];

// ---------------- small helpers ----------------
__device__ __forceinline__ uint32_t pack2(float x, float y, uint32_t &lo)
{
    __nv_bfloat16 xh = __float2bfloat16(x);
    __nv_bfloat16 yh = __float2bfloat16(y);
    __nv_bfloat162 H; H.x = xh; H.y = yh;
    __nv_bfloat162 L; L.x = __float2bfloat16(x - __bfloat162float(xh));
    L.y = __float2bfloat16(y - __bfloat162float(yh));
    lo = *reinterpret_cast<const uint32_t*>(&L);
    return *reinterpret_cast<const uint32_t*>(&H);
}
__device__ __forceinline__ uint32_t packh2(float x, float y)
{
    __half2 H; H.x = __float2half(x); H.y = __float2half(y);
    return *reinterpret_cast<const uint32_t*>(&H);
}
__device__ __forceinline__ uint32_t packh2_split(float x, float y, uint32_t &lo)
{
    __half xh = __float2half(x);
    __half yh = __float2half(y);
    __half2 H; H.x = xh; H.y = yh;
    __half2 L; L.x = __float2half(x - __half2float(xh));
    L.y = __float2half(y - __half2float(yh));
    lo = *reinterpret_cast<const uint32_t*>(&L);
    return *reinterpret_cast<const uint32_t*>(&H);
}

__device__ __forceinline__ float gelu_tanh(float x) {
    float x3 = x*x*x;
    return 0.5f * x * (1.0f + tanhf(0.7978845608028654f * (x + 0.044715f * x3)));
}

__device__ __forceinline__ float ex2f(float x) {
    float y;
    asm("ex2.approx.f32 %0, %1;" : "=f"(y) : "f"(x));
    return y;
}

__device__ __forceinline__ uint32_t smem_u32(const void* p) {
    uint32_t a;
    asm("{ .reg .u64 t; cvta.to.shared.u64 t, %1; cvt.u32.u64 %0, t; }"
        : "=r"(a) : "l"(p));
    return a;
}
__device__ __forceinline__ void cpasync16(uint32_t dst, const void* src) {
    asm volatile("cp.async.cg.shared.global [%0], [%1], 16;"
                 :: "r"(dst), "l"(__cvta_generic_to_global(src)));
}
__device__ __forceinline__ void cp_commit() {
    asm volatile("cp.async.commit_group;");
}
template<int N>
__device__ __forceinline__ void cp_wait() {
    asm volatile("cp.async.wait_group %0;" :: "n"(N));
}
__device__ __forceinline__ void ldsm4(uint32_t& r0, uint32_t& r1,
                                      uint32_t& r2, uint32_t& r3, uint32_t addr) {
    asm volatile("ldmatrix.sync.aligned.m8n8.x4.shared.b16 {%0,%1,%2,%3}, [%4];"
                 : "=r"(r0), "=r"(r1), "=r"(r2), "=r"(r3) : "r"(addr));
}
__device__ __forceinline__ void ldsm4t(uint32_t& r0, uint32_t& r1,
                                       uint32_t& r2, uint32_t& r3, uint32_t addr) {
    asm volatile("ldmatrix.sync.aligned.m8n8.x4.trans.shared.b16 {%0,%1,%2,%3}, [%4];"
                 : "=r"(r0), "=r"(r1), "=r"(r2), "=r"(r3) : "r"(addr));
}
__device__ __forceinline__ void mma16816(float* d,
    uint32_t a0, uint32_t a1, uint32_t a2, uint32_t a3,
    uint32_t b0, uint32_t b1)
{
    asm volatile(
        "mma.sync.aligned.m16n8k16.row.col.f32.bf16.bf16.f32 "
        "{%0,%1,%2,%3}, {%4,%5,%6,%7}, {%8,%9}, {%0,%1,%2,%3};"
        : "+f"(d[0]), "+f"(d[1]), "+f"(d[2]), "+f"(d[3])
        : "r"(a0), "r"(a1), "r"(a2), "r"(a3), "r"(b0), "r"(b1));
}
__device__ __forceinline__ void mma16816h(float* d,
    uint32_t a0, uint32_t a1, uint32_t a2, uint32_t a3,
    uint32_t b0, uint32_t b1)
{
    asm volatile(
        "mma.sync.aligned.m16n8k16.row.col.f32.f16.f16.f32 "
        "{%0,%1,%2,%3}, {%4,%5,%6,%7}, {%8,%9}, {%0,%1,%2,%3};"
        : "+f"(d[0]), "+f"(d[1]), "+f"(d[2]), "+f"(d[3])
        : "r"(a0), "r"(a1), "r"(a2), "r"(a3), "r"(b0), "r"(b1));
}

// ---------------- weight pre-split ----------------
__global__ void split_kernel(const float* __restrict__ s,
                             __half* __restrict__ h,
                             __half* __restrict__ l, long n4)
{
    long stride = (long)gridDim.x * blockDim.x;
    for (long i = (long)blockIdx.x * blockDim.x + threadIdx.x; i < n4; i += stride) {
        float4 v = ((const float4*)s)[i];
        uint2 H, L;
        H.x = packh2_split(v.x, v.y, L.x);
        H.y = packh2_split(v.z, v.w, L.y);
        ((uint2*)h)[i] = H;
        ((uint2*)l)[i] = L;
    }
}
// hi-only convert (lm_head weights)
__global__ void conv_kernel(const float* __restrict__ s,
                            __half* __restrict__ h, long n4)
{
    long stride = (long)gridDim.x * blockDim.x;
    for (long i = (long)blockIdx.x * blockDim.x + threadIdx.x; i < n4; i += stride) {
        float4 v = ((const float4*)s)[i];
        uint2 H;
        H.x = packh2(v.x, v.y);
        H.y = packh2(v.z, v.w);
        ((uint2*)h)[i] = H;
    }
}

// ---------------- embedding ----------------
__global__ void embed_kernel(const int* __restrict__ idx,
                             const float* __restrict__ wte,
                             const float* __restrict__ wpe,
                             float* __restrict__ x)
{
    int m = blockIdx.x;
    int t = m & (TT-1);
    int tok = idx[m];
    const float* we = wte + (size_t)tok * CC;
    const float* wp = wpe + (size_t)t * CC;
    float* xr = x + (size_t)m * CC;
    for (int c = threadIdx.x; c < CC; c += blockDim.x)
        xr[c] = we[c] + wp[c];
}

// ---------------- layernorm -> fp16 ----------
__global__ void ln_kernel(const float* __restrict__ x,
                          const float* __restrict__ w,
                          const float* __restrict__ b,
                          __half* __restrict__ yh)
{
    __shared__ float red[16];
    int row  = blockIdx.x;
    int tid  = threadIdx.x;
    int lane = tid & 31;
    int warp = tid >> 5;
    const float* xr = x + (size_t)row * CC;

    float v0 = xr[tid], v1 = xr[tid+256], v2 = xr[tid+512];
    float s = v0 + v1 + v2;
    #pragma unroll
    for (int o = 16; o; o >>= 1) s += __shfl_xor_sync(0xffffffffu, s, o);
    if (!lane) red[warp] = s;
    __syncthreads();
    float mu = (red[0]+red[1]+red[2]+red[3]+red[4]+red[5]+red[6]+red[7]) * (1.0f/CC);

    float d0 = v0-mu, d1 = v1-mu, d2 = v2-mu;
    float q = d0*d0 + d1*d1 + d2*d2;
    #pragma unroll
    for (int o = 16; o; o >>= 1) q += __shfl_xor_sync(0xffffffffu, q, o);
    if (!lane) red[8+warp] = q;
    __syncthreads();
    float rstd = rsqrtf((red[8]+red[9]+red[10]+red[11]+red[12]+red[13]+red[14]+red[15])
                        * (1.0f/CC) + 1e-5f);

    size_t base = (size_t)row * CC;
    #pragma unroll
    for (int j = 0; j < 3; j++) {
        int c = tid + j*256;
        float v = (j==0?d0:(j==1?d1:d2))*rstd*w[c] + b[c];
        yh[base+c] = __float2half(v);
    }
}

// ---------------- fp16 HMMA GEMM, BMx128 tile, 1- or 2-term weights ----------
// Y = X @ W^T (+bias)(gelu)(+res). X fp16, W fp16 hi(+lo).
// BM in {64,128}. 8 warps (2x4); warp tile (BM/2)x32. BK=32, 3-stage cp.async.
#define BKG 32

template<int BM, bool TWOTERM, bool GELU, bool RES, bool OUTHALF>
__global__ void __launch_bounds__(256, (BM == 64) ? 2 : 1)
gemm_hmma(const __half* __restrict__ X,
          const __half* __restrict__ Wh, const __half* __restrict__ Wl,
          const float* __restrict__ bias, const float* __restrict__ res,
          float* __restrict__ Y, __half* __restrict__ Yh,
          int M, int N, int K)
{
    constexpr int FM     = BM / 32;                 // m16 frags per warp
    constexpr int ATILE  = BM * 64;                 // A tile bytes
    constexpr int BTILE  = 8192;                    // B tile bytes (128 rows)
    constexpr int STAGEB = ATILE + (TWOTERM ? 2 : 1) * BTILE;

    extern __shared__ char sm[];
    const uint32_t sb = smem_u32(sm);

    const int tid  = threadIdx.x;
    const int lane = tid & 31;
    const int warp = tid >> 5;
    const int wm   = warp & 1;
    const int wn   = warp >> 1;
    const int g    = lane >> 2;
    const int tg   = lane & 3;
    const int bm   = blockIdx.x * BM;
    const int bn   = blockIdx.y * 128;

    float d[FM][4][4];
    #pragma unroll
    for (int i = 0; i < FM; i++)
        #pragma unroll
        for (int j = 0; j < 4; j++) {
            d[i][j][0]=0.f; d[i][j][1]=0.f; d[i][j][2]=0.f; d[i][j][3]=0.f;
        }

    // ---- global->smem mappings ----
    // A: BM rows, BM/64 chunks per thread
    int lrA, lcA0;
    if (BM == 128) { lrA = tid >> 1; lcA0 = (tid & 1) * 2; }
    else           { lrA = tid >> 2; lcA0 = tid & 3; }
    const __half* x_p = X + (size_t)(bm + lrA)*K;
    uint32_t soA[2];
    #pragma unroll
    for (int i = 0; i < (BM == 128 ? 2 : 1); i++)
        soA[i] = (uint32_t)(lrA*64 + (((lcA0+i) ^ ((lrA>>1)&3)) << 4));

    // B: 128 rows, 2 chunks per thread
    const int lrB  = tid >> 1;
    const int lcB0 = (tid & 1) * 2;
    const __half* wh_p = Wh + (size_t)(bn + lrB)*K;
    const __half* wl_p = TWOTERM ? (Wl + (size_t)(bn + lrB)*K) : nullptr;
    uint32_t soB[2];
    #pragma unroll
    for (int i = 0; i < 2; i++)
        soB[i] = (uint32_t)(lrB*64 + (((lcB0+i) ^ ((lrB>>1)&3)) << 4));

    // ---- ldmatrix fragment addresses ----
    uint32_t a_off[FM][2], b_off[2][2];
    {
        int arow = wm*(BM/2) + (lane & 15);
        int ln16 = lane >> 4;
        #pragma unroll
        for (int fm = 0; fm < FM; fm++) {
            int r = arow + fm*16;
            #pragma unroll
            for (int ks = 0; ks < 2; ks++) {
                int c = ks*2 + ln16;
                a_off[fm][ks] = (uint32_t)(r*64 + ((c ^ ((r>>1)&3)) << 4));
            }
        }
        int q = lane >> 3;
        int brow = wn*32 + ((q >> 1) << 3) + (lane & 7);
        int cadd = q & 1;
        #pragma unroll
        for (int fnp = 0; fnp < 2; fnp++) {
            int r = brow + fnp*16;
            #pragma unroll
            for (int ks = 0; ks < 2; ks++) {
                int c = ks*2 + cadd;
                b_off[fnp][ks] = (uint32_t)(r*64 + ((c ^ ((r>>1)&3)) << 4));
            }
        }
    }

    const int NT = K / BKG;

    auto issue_stage = [&](int stage, uint32_t base) {
        const int k0 = stage * BKG;
        #pragma unroll
        for (int i = 0; i < (BM == 128 ? 2 : 1); i++) {
            int c = lcA0 + i;
            cpasync16(base + soA[i], (const char*)(x_p + k0) + c*16);
        }
        #pragma unroll
        for (int i = 0; i < 2; i++) {
            int c = lcB0 + i;
            cpasync16(base + ATILE + soB[i], (const char*)(wh_p + k0) + c*16);
            if (TWOTERM)
                cpasync16(base + ATILE + BTILE + soB[i], (const char*)(wl_p + k0) + c*16);
        }
    };

    #pragma unroll
    for (int s = 0; s < 2; s++) {
        issue_stage(s, sb + (uint32_t)s * STAGEB);
        cp_commit();
    }

    int bufc = 0;
    for (int t = 0; t < NT; t++) {
        cp_wait<1>();
        __syncthreads();

        if (t + 2 < NT) {
            int bufs = bufc + 2; if (bufs >= 3) bufs -= 3;
            issue_stage(t + 2, sb + (uint32_t)bufs * STAGEB);
        }
        cp_commit();

        {
            uint32_t base = sb + (uint32_t)bufc * STAGEB;
            uint32_t aX = base;
            uint32_t bH = base + ATILE, bL = base + ATILE + BTILE;

            #pragma unroll
            for (int ks = 0; ks < 2; ks++) {
                uint32_t ah[FM][4], bh[4][2], bl[4][2];
                #pragma unroll
                for (int fm = 0; fm < FM; fm++)
                    ldsm4(ah[fm][0], ah[fm][1], ah[fm][2], ah[fm][3], aX + a_off[fm][ks]);
                #pragma unroll
                for (int fnp = 0; fnp < 2; fnp++) {
                    uint32_t r0, r1, r2, r3;
                    ldsm4(r0, r1, r2, r3, bH + b_off[fnp][ks]);
                    bh[fnp*2][0]=r0; bh[fnp*2][1]=r1; bh[fnp*2+1][0]=r2; bh[fnp*2+1][1]=r3;
                    if (TWOTERM) {
                        ldsm4(r0, r1, r2, r3, bL + b_off[fnp][ks]);
                        bl[fnp*2][0]=r0; bl[fnp*2][1]=r1; bl[fnp*2+1][0]=r2; bl[fnp*2+1][1]=r3;
                    }
                }
                #pragma unroll
                for (int fm = 0; fm < FM; fm++)
                    #pragma unroll
                    for (int fn = 0; fn < 4; fn++) {
                        mma16816h(d[fm][fn], ah[fm][0],ah[fm][1],ah[fm][2],ah[fm][3],
                                  bh[fn][0], bh[fn][1]);
                        if (TWOTERM)
                            mma16816h(d[fm][fn], ah[fm][0],ah[fm][1],ah[fm][2],ah[fm][3],
                                      bl[fn][0], bl[fn][1]);
                    }
            }
        }
        bufc = (bufc + 1 == 3) ? 0 : bufc + 1;
    }

    #pragma unroll
    for (int fm = 0; fm < FM; fm++) {
        int mrow = bm + wm*(BM/2) + fm*16 + g;
        #pragma unroll
        for (int half = 0; half < 2; half++) {
            int m = mrow + half*8;
            #pragma unroll
            for (int fn = 0; fn < 4; fn++) {
                int n0 = bn + wn*32 + fn*8 + tg*2;
                float v0 = d[fm][fn][half*2+0];
                float v1 = d[fm][fn][half*2+1];
                if (bias) { v0 += bias[n0]; v1 += bias[n0+1]; }
                if (GELU) { v0 = gelu_tanh(v0); v1 = gelu_tanh(v1); }
                if (RES) {
                    float2 rv = *(const float2*)&res[(size_t)m*N + n0];
                    v0 += rv.x; v1 += rv.y;
                }
                if (OUTHALF) {
                    *(uint32_t*)&Yh[(size_t)m*N + n0] = packh2(v0, v1);
                } else {
                    float2 o2; o2.x = v0; o2.y = v1;
                    *(float2*)&Y[(size_t)m*N + n0] = o2;
                }
            }
        }
    }
}

// smem sizes per instantiation
#define SM64_2  (3*(64*64  + 2*8192))   // 61440
#define SM128_1 (3*(128*64 + 1*8192))   // 49152

// ---------------- tensor-core flash attention (bf16 3-term, fp16 output) ----
__global__ void __launch_bounds__(256)
attn_tc(const float* __restrict__ qkv, __half* __restrict__ yh)
{
    __shared__ char smem[32768];
    const uint32_t sb = smem_u32(smem);
    const int tid  = threadIdx.x;
    const int lane = tid & 31;
    const int w    = tid >> 5;
    const int g    = lane >> 2;
    const int tg   = lane & 3;
    const int qt   = gridDim.x - 1 - blockIdx.x;
    const int h    = blockIdx.y;
    const int b    = blockIdx.z;
    const int q0   = qt * 128;

    const float SC = 0.18033688011112042f;   // 0.125 * log2(e)

    {
        int r  = tid >> 1;
        int dh = (tid & 1) * 32;
        const float* src = qkv + (size_t)(b*TT + q0 + r)*C3 + h*DD + dh;
        #pragma unroll
        for (int cc = 0; cc < 4; cc++) {
            float4 v0 = *(const float4*)(src + cc*8);
            float4 v1 = *(const float4*)(src + cc*8 + 4);
            uint4 Hc, Lc;
            Hc.x = pack2(v0.x*SC, v0.y*SC, Lc.x);
            Hc.y = pack2(v0.z*SC, v0.w*SC, Lc.y);
            Hc.z = pack2(v1.x*SC, v1.y*SC, Lc.z);
            Hc.w = pack2(v1.z*SC, v1.w*SC, Lc.w);
            int c = (dh >> 3) + cc;
            uint32_t off = (uint32_t)(r*128 + ((c ^ (r & 7)) << 4));
            *(uint4*)(smem + off)         = Hc;
            *(uint4*)(smem + 16384 + off) = Lc;
        }
    }
    __syncthreads();

    uint32_t qh[4][4], ql[4][4];
    #pragma unroll
    for (int kk = 0; kk < 4; kk++) {
        int row = w*16 + (lane & 15);
        int c   = kk*2 + (lane >> 4);
        uint32_t off = (uint32_t)(row*128 + ((c ^ (row & 7)) << 4));
        ldsm4(qh[kk][0], qh[kk][1], qh[kk][2], qh[kk][3], sb + off);
        ldsm4(ql[kk][0], ql[kk][1], ql[kk][2], ql[kk][3], sb + 16384 + off);
    }

    float o[8][4];
    #pragma unroll
    for (int j = 0; j < 8; j++) { o[j][0]=0.f; o[j][1]=0.f; o[j][2]=0.f; o[j][3]=0.f; }
    float mrow0 = -1e30f, mrow1 = -1e30f, lrow0 = 0.f, lrow1 = 0.f;

    const int qrow0 = q0 + w*16 + g;
    const int nk  = (q0 + 128) >> 6;
    const int nkw = ((q0 + w*16 + 15) >> 6) + 1;

    const uint32_t KH_ = 0u, KL_ = 8192u, VH_ = 16384u, VL_ = 24576u;

    for (int kt = 0; kt < nk; kt++) {
        __syncthreads();

        {
            int r  = tid >> 2;
            int dq = (tid & 3) * 16;
            const float* kr = qkv + (size_t)(b*TT + kt*64 + r)*C3 + CC + h*DD + dq;
            const float* vr = kr + CC;
            #pragma unroll
            for (int half = 0; half < 2; half++) {
                int c = (dq >> 3) + half;
                uint32_t off = (uint32_t)(r*128 + ((c ^ (r & 7)) << 4));
                float4 k0 = *(const float4*)(kr + half*8);
                float4 k1 = *(const float4*)(kr + half*8 + 4);
                uint4 Hc, Lc;
                Hc.x = pack2(k0.x, k0.y, Lc.x);
                Hc.y = pack2(k0.z, k0.w, Lc.y);
                Hc.z = pack2(k1.x, k1.y, Lc.z);
                Hc.w = pack2(k1.z, k1.w, Lc.w);
                *(uint4*)(smem + KH_ + off) = Hc;
                *(uint4*)(smem + KL_ + off) = Lc;
                float4 w0 = *(const float4*)(vr + half*8);
                float4 w1 = *(const float4*)(vr + half*8 + 4);
                Hc.x = pack2(w0.x, w0.y, Lc.x);
                Hc.y = pack2(w0.z, w0.w, Lc.y);
                Hc.z = pack2(w1.x, w1.y, Lc.z);
                Hc.w = pack2(w1.z, w1.w, Lc.w);
                *(uint4*)(smem + VH_ + off) = Hc;
                *(uint4*)(smem + VL_ + off) = Lc;
            }
        }
        __syncthreads();

        if (kt >= nkw) continue;

        float s[8][4];
        #pragma unroll
        for (int j = 0; j < 8; j++) { s[j][0]=0.f; s[j][1]=0.f; s[j][2]=0.f; s[j][3]=0.f; }

        #pragma unroll
        for (int kk = 0; kk < 4; kk++) {
            int q4 = lane >> 3;
            #pragma unroll
            for (int jj = 0; jj < 4; jj++) {
                int row = jj*16 + ((q4 >> 1) << 3) + (lane & 7);
                int c   = kk*2 + (q4 & 1);
                uint32_t off = (uint32_t)(row*128 + ((c ^ (row & 7)) << 4));
                uint32_t h0,h1,h2,h3, l0,l1,l2,l3;
                ldsm4(h0, h1, h2, h3, sb + KH_ + off);
                ldsm4(l0, l1, l2, l3, sb + KL_ + off);
                mma16816(s[2*jj  ], qh[kk][0],qh[kk][1],qh[kk][2],qh[kk][3], h0, h1);
                mma16816(s[2*jj  ], ql[kk][0],ql[kk][1],ql[kk][2],ql[kk][3], h0, h1);
                mma16816(s[2*jj  ], qh[kk][0],qh[kk][1],qh[kk][2],qh[kk][3], l0, l1);
                mma16816(s[2*jj+1], qh[kk][0],qh[kk][1],qh[kk][2],qh[kk][3], h2, h3);
                mma16816(s[2*jj+1], ql[kk][0],ql[kk][1],ql[kk][2],ql[kk][3], h2, h3);
                mma16816(s[2*jj+1], qh[kk][0],qh[kk][1],qh[kk][2],qh[kk][3], l2, l3);
            }
        }

        if (kt*64 + 63 > q0 + w*16) {
            #pragma unroll
            for (int j = 0; j < 8; j++) {
                int c0 = kt*64 + j*8 + 2*tg;
                if (c0     > qrow0)     s[j][0] = -1e30f;
                if (c0 + 1 > qrow0)     s[j][1] = -1e30f;
                if (c0     > qrow0 + 8) s[j][2] = -1e30f;
                if (c0 + 1 > qrow0 + 8) s[j][3] = -1e30f;
            }
        }

        float mx0 = -1e30f, mx1 = -1e30f;
        #pragma unroll
        for (int j = 0; j < 8; j++) {
            mx0 = fmaxf(mx0, fmaxf(s[j][0], s[j][1]));
            mx1 = fmaxf(mx1, fmaxf(s[j][2], s[j][3]));
        }
        mx0 = fmaxf(mx0, __shfl_xor_sync(0xffffffffu, mx0, 1));
        mx0 = fmaxf(mx0, __shfl_xor_sync(0xffffffffu, mx0, 2));
        mx1 = fmaxf(mx1, __shfl_xor_sync(0xffffffffu, mx1, 1));
        mx1 = fmaxf(mx1, __shfl_xor_sync(0xffffffffu, mx1, 2));

        float mn0 = fmaxf(mrow0, mx0), mn1 = fmaxf(mrow1, mx1);
        float a0  = ex2f(mrow0 - mn0), a1  = ex2f(mrow1 - mn1);
        float ls0 = 0.f, ls1 = 0.f;
        #pragma unroll
        for (int j = 0; j < 8; j++) {
            s[j][0] = ex2f(s[j][0] - mn0);  ls0 += s[j][0];
            s[j][1] = ex2f(s[j][1] - mn0);  ls0 += s[j][1];
            s[j][2] = ex2f(s[j][2] - mn1);  ls1 += s[j][2];
            s[j][3] = ex2f(s[j][3] - mn1);  ls1 += s[j][3];
        }
        ls0 += __shfl_xor_sync(0xffffffffu, ls0, 1);
        ls0 += __shfl_xor_sync(0xffffffffu, ls0, 2);
        ls1 += __shfl_xor_sync(0xffffffffu, ls1, 1);
        ls1 += __shfl_xor_sync(0xffffffffu, ls1, 2);
        lrow0 = lrow0*a0 + ls0;  lrow1 = lrow1*a1 + ls1;
        mrow0 = mn0;  mrow1 = mn1;
        #pragma unroll
        for (int j = 0; j < 8; j++) {
            o[j][0] *= a0; o[j][1] *= a0; o[j][2] *= a1; o[j][3] *= a1;
        }

        uint32_t* sp = (uint32_t*)s;
        #pragma unroll
        for (int kk = 0; kk < 4; kk++) {
            uint32_t lo;
            uint32_t h0 = pack2(s[2*kk][0],   s[2*kk][1],   lo);
            sp[kk*8+0] = h0; sp[kk*8+1] = lo;
            uint32_t h1 = pack2(s[2*kk][2],   s[2*kk][3],   lo);
            sp[kk*8+2] = h1; sp[kk*8+3] = lo;
            uint32_t h2 = pack2(s[2*kk+1][0], s[2*kk+1][1], lo);
            sp[kk*8+4] = h2; sp[kk*8+5] = lo;
            uint32_t h3 = pack2(s[2*kk+1][2], s[2*kk+1][3], lo);
            sp[kk*8+6] = h3; sp[kk*8+7] = lo;
        }

        #pragma unroll
        for (int kk = 0; kk < 4; kk++) {
            uint32_t pa0 = sp[kk*8+0], pa1 = sp[kk*8+2], pa2 = sp[kk*8+4], pa3 = sp[kk*8+6];
            uint32_t pb0 = sp[kk*8+1], pb1 = sp[kk*8+3], pb2 = sp[kk*8+5], pb3 = sp[kk*8+7];
            int tl = lane >> 3;
            #pragma unroll
            for (int jj = 0; jj < 4; jj++) {
                int row = kk*16 + ((tl & 1) << 3) + (lane & 7);
                int c   = jj*2 + (tl >> 1);
                uint32_t off = (uint32_t)(row*128 + ((c ^ (row & 7)) << 4));
                uint32_t v0,v1,v2,v3, u0,u1,u2,u3;
                ldsm4t(v0, v1, v2, v3, sb + VH_ + off);
                ldsm4t(u0, u1, u2, u3, sb + VL_ + off);
                mma16816(o[2*jj  ], pa0, pa1, pa2, pa3, v0, v1);
                mma16816(o[2*jj  ], pb0, pb1, pb2, pb3, v0, v1);
                mma16816(o[2*jj  ], pa0, pa1, pa2, pa3, u0, u1);
                mma16816(o[2*jj+1], pa0, pa1, pa2, pa3, v2, v3);
                mma16816(o[2*jj+1], pb0, pb1, pb2, pb3, v2, v3);
                mma16816(o[2*jj+1], pa0, pa1, pa2, pa3, u2, u3);
            }
        }
    }

    float inv0 = 1.0f / lrow0, inv1 = 1.0f / lrow1;
    #pragma unroll
    for (int j = 0; j < 8; j++) {
        size_t oidx = (size_t)(b*TT + qrow0)*CC + h*DD + j*8 + 2*tg;
        *(uint32_t*)&yh[oidx] = packh2(o[j][0]*inv0, o[j][1]*inv0);
        oidx += (size_t)8*CC;
        *(uint32_t*)&yh[oidx] = packh2(o[j][2]*inv1, o[j][3]*inv1);
    }
}

// ---------------- launch ----------------
extern "C" void kernel_launch(void* const* d_in, const int* in_sizes, int n_in,
                              void* d_out, int out_size)
{
    (void)in_sizes; (void)n_in; (void)out_size;
    const int*   idx     = (const int*)  d_in[0];
    const float* wte     = (const float*)d_in[1];
    const float* wpe     = (const float*)d_in[2];
    const float* ln1w    = (const float*)d_in[3];
    const float* ln1b    = (const float*)d_in[4];
    const float* qkvw    = (const float*)d_in[5];
    const float* qkvb    = (const float*)d_in[6];
    const float* projw   = (const float*)d_in[7];
    const float* projb   = (const float*)d_in[8];
    const float* ln2w    = (const float*)d_in[9];
    const float* ln2b    = (const float*)d_in[10];
    const float* fcw     = (const float*)d_in[11];
    const float* fcb     = (const float*)d_in[12];
    const float* fcprojw = (const float*)d_in[13];
    const float* fcprojb = (const float*)d_in[14];
    const float* lnfw    = (const float*)d_in[15];
    const float* lnfb    = (const float*)d_in[16];
    float* out = (float*)d_out;

    float *x, *qkv;
    __half *ln, *att, *act;
    __half *qkvwh, *qkvwl, *projwh, *projwl, *fcwh, *fcwl, *fcpwh, *fcpwl, *wteh;
    cudaGetSymbolAddress((void**)&x,    g_x);
    cudaGetSymbolAddress((void**)&qkv,  g_qkv);
    cudaGetSymbolAddress((void**)&ln,   g_ln);
    cudaGetSymbolAddress((void**)&att,  g_att);
    cudaGetSymbolAddress((void**)&act,  g_act);
    cudaGetSymbolAddress((void**)&qkvwh, g_qkvw_h); cudaGetSymbolAddress((void**)&qkvwl, g_qkvw_l);
    cudaGetSymbolAddress((void**)&projwh,g_projw_h);cudaGetSymbolAddress((void**)&projwl,g_projw_l);
    cudaGetSymbolAddress((void**)&fcwh, g_fcw_h);  cudaGetSymbolAddress((void**)&fcwl, g_fcw_l);
    cudaGetSymbolAddress((void**)&fcpwh,g_fcpw_h); cudaGetSymbolAddress((void**)&fcpwl,g_fcpw_l);
    cudaGetSymbolAddress((void**)&wteh, g_wte_h);

    cudaFuncSetAttribute(gemm_hmma<64,true,false,false,false>, cudaFuncAttributeMaxDynamicSharedMemorySize, SM64_2);
    cudaFuncSetAttribute(gemm_hmma<64,true,false,true ,false>, cudaFuncAttributeMaxDynamicSharedMemorySize, SM64_2);
    cudaFuncSetAttribute(gemm_hmma<64,true,true ,false,true >, cudaFuncAttributeMaxDynamicSharedMemorySize, SM64_2);
    cudaFuncSetAttribute(gemm_hmma<128,false,false,false,false>, cudaFuncAttributeMaxDynamicSharedMemorySize, SM128_1);

    const int SB = 1184;
    split_kernel<<<SB, 256>>>(qkvw,    qkvwh,  qkvwl,  (long)LL*C3*CC/4);
    split_kernel<<<SB, 256>>>(projw,   projwh, projwl, (long)LL*CC*CC/4);
    split_kernel<<<SB, 256>>>(fcw,     fcwh,   fcwl,   (long)LL*C4*CC/4);
    split_kernel<<<SB, 256>>>(fcprojw, fcpwh,  fcpwl,  (long)LL*CC*C4/4);
    conv_kernel <<<SB, 256>>>(wte,     wteh,           (long)VP*CC/4);

    embed_kernel<<<MROWS, 256>>>(idx, wte, wpe, x);

    for (int l = 0; l < LL; l++) {
        ln_kernel<<<MROWS, 256>>>(x, ln1w + l*CC, ln1b + l*CC, ln);

        gemm_hmma<64,true,false,false,false><<<dim3(MROWS/64, C3/128), 256, SM64_2>>>(
            ln, qkvwh + (size_t)l*C3*CC, qkvwl + (size_t)l*C3*CC,
            qkvb + (size_t)l*C3, nullptr, qkv, nullptr, MROWS, C3, CC);

        attn_tc<<<dim3(TT/128, HH, BATCH), 256>>>(qkv, att);

        gemm_hmma<64,true,false,true,false><<<dim3(MROWS/64, CC/128), 256, SM64_2>>>(
            att, projwh + (size_t)l*CC*CC, projwl + (size_t)l*CC*CC,
            projb + (size_t)l*CC, x, x, nullptr, MROWS, CC, CC);

        ln_kernel<<<MROWS, 256>>>(x, ln2w + l*CC, ln2b + l*CC, ln);

        gemm_hmma<64,true,true,false,true><<<dim3(MROWS/64, C4/128), 256, SM64_2>>>(
            ln, fcwh + (size_t)l*C4*CC, fcwl + (size_t)l*C4*CC,
            fcb + (size_t)l*C4, nullptr, nullptr, act, MROWS, C4, CC);

        gemm_hmma<64,true,false,true,false><<<dim3(MROWS/64, CC/128), 256, SM64_2>>>(
            act, fcpwh + (size_t)l*CC*C4, fcpwl + (size_t)l*CC*C4,
            fcprojb + (size_t)l*CC, x, x, nullptr, MROWS, CC, C4);
    }

    ln_kernel<<<MROWS, 256>>>(x, lnfw, lnfb, ln);

    gemm_hmma<128,false,false,false,false><<<dim3(MROWS/128, VP/128), 256, SM128_1>>>(
        ln, wteh, nullptr, nullptr, nullptr, out, nullptr, MROWS, VP, CC);
}

// round 11
// speedup vs baseline: 1.0941x; 1.0941x over previous
#include <cuda_runtime.h>
#include <cuda_bf16.h>
#include <cuda_fp16.h>
#include <math.h>
#include <stdint.h>

// ---------------- problem constants ----------------
#define BATCH 2
#define TT    1024
#define CC    768
#define HH    12
#define DD    64
#define LL    12
#define MROWS (BATCH*TT)      // 2048
#define C3    (3*CC)          // 2304
#define C4    (4*CC)          // 3072
#define VP    50304

// ---------------- scratch (device globals) ----------
__device__ float g_x  [MROWS*CC];
__device__ float g_qkv[MROWS*C3];

__device__ __half g_ln [MROWS*CC];
__device__ __half g_att[MROWS*CC];
__device__ __half g_act[MROWS*C4];

__device__ __half g_qkvw_h [(size_t)LL*C3*CC], g_qkvw_l [(size_t)LL*C3*CC];
__device__ __half g_projw_h[(size_t)LL*CC*CC], g_projw_l[(size_t)LL*CC*CC];
__device__ __half g_fcw_h  [(size_t)LL*C4*CC], g_fcw_l  [(size_t)LL*C4*CC];
__device__ __half g_fcpw_h [(size_t)LL*CC*C4], g_fcpw_l [(size_t)LL*CC*C4];
__device__ __half g_wte_h  [(size_t)VP*CC];

// ---------------- small helpers ----------------
__device__ __forceinline__ uint32_t pack2(float x, float y, uint32_t &lo)
{
    __nv_bfloat16 xh = __float2bfloat16(x);
    __nv_bfloat16 yh = __float2bfloat16(y);
    __nv_bfloat162 H; H.x = xh; H.y = yh;
    __nv_bfloat162 L; L.x = __float2bfloat16(x - __bfloat162float(xh));
    L.y = __float2bfloat16(y - __bfloat162float(yh));
    lo = *reinterpret_cast<const uint32_t*>(&L);
    return *reinterpret_cast<const uint32_t*>(&H);
}
__device__ __forceinline__ uint32_t packh2(float x, float y)
{
    __half2 H; H.x = __float2half(x); H.y = __float2half(y);
    return *reinterpret_cast<const uint32_t*>(&H);
}
__device__ __forceinline__ uint32_t packh2_split(float x, float y, uint32_t &lo)
{
    __half xh = __float2half(x);
    __half yh = __float2half(y);
    __half2 H; H.x = xh; H.y = yh;
    __half2 L; L.x = __float2half(x - __half2float(xh));
    L.y = __float2half(y - __half2float(yh));
    lo = *reinterpret_cast<const uint32_t*>(&L);
    return *reinterpret_cast<const uint32_t*>(&H);
}

__device__ __forceinline__ float gelu_tanh(float x) {
    float x3 = x*x*x;
    return 0.5f * x * (1.0f + tanhf(0.7978845608028654f * (x + 0.044715f * x3)));
}

__device__ __forceinline__ float ex2f(float x) {
    float y;
    asm("ex2.approx.f32 %0, %1;" : "=f"(y) : "f"(x));
    return y;
}

__device__ __forceinline__ uint32_t smem_u32(const void* p) {
    uint32_t a;
    asm("{ .reg .u64 t; cvta.to.shared.u64 t, %1; cvt.u32.u64 %0, t; }"
        : "=r"(a) : "l"(p));
    return a;
}
__device__ __forceinline__ void cpasync16(uint32_t dst, const void* src) {
    asm volatile("cp.async.cg.shared.global [%0], [%1], 16;"
                 :: "r"(dst), "l"(__cvta_generic_to_global(src)));
}
__device__ __forceinline__ void cp_commit() {
    asm volatile("cp.async.commit_group;");
}
template<int N>
__device__ __forceinline__ void cp_wait() {
    asm volatile("cp.async.wait_group %0;" :: "n"(N));
}
__device__ __forceinline__ void ldsm4(uint32_t& r0, uint32_t& r1,
                                      uint32_t& r2, uint32_t& r3, uint32_t addr) {
    asm volatile("ldmatrix.sync.aligned.m8n8.x4.shared.b16 {%0,%1,%2,%3}, [%4];"
                 : "=r"(r0), "=r"(r1), "=r"(r2), "=r"(r3) : "r"(addr));
}
__device__ __forceinline__ void ldsm4t(uint32_t& r0, uint32_t& r1,
                                       uint32_t& r2, uint32_t& r3, uint32_t addr) {
    asm volatile("ldmatrix.sync.aligned.m8n8.x4.trans.shared.b16 {%0,%1,%2,%3}, [%4];"
                 : "=r"(r0), "=r"(r1), "=r"(r2), "=r"(r3) : "r"(addr));
}
__device__ __forceinline__ void mma16816(float* d,
    uint32_t a0, uint32_t a1, uint32_t a2, uint32_t a3,
    uint32_t b0, uint32_t b1)
{
    asm volatile(
        "mma.sync.aligned.m16n8k16.row.col.f32.bf16.bf16.f32 "
        "{%0,%1,%2,%3}, {%4,%5,%6,%7}, {%8,%9}, {%0,%1,%2,%3};"
        : "+f"(d[0]), "+f"(d[1]), "+f"(d[2]), "+f"(d[3])
        : "r"(a0), "r"(a1), "r"(a2), "r"(a3), "r"(b0), "r"(b1));
}
__device__ __forceinline__ void mma16816h(float* d,
    uint32_t a0, uint32_t a1, uint32_t a2, uint32_t a3,
    uint32_t b0, uint32_t b1)
{
    asm volatile(
        "mma.sync.aligned.m16n8k16.row.col.f32.f16.f16.f32 "
        "{%0,%1,%2,%3}, {%4,%5,%6,%7}, {%8,%9}, {%0,%1,%2,%3};"
        : "+f"(d[0]), "+f"(d[1]), "+f"(d[2]), "+f"(d[3])
        : "r"(a0), "r"(a1), "r"(a2), "r"(a3), "r"(b0), "r"(b1));
}

// ---------------- weight pre-split ----------------
__global__ void split_kernel(const float* __restrict__ s,
                             __half* __restrict__ h,
                             __half* __restrict__ l, long n4)
{
    long stride = (long)gridDim.x * blockDim.x;
    for (long i = (long)blockIdx.x * blockDim.x + threadIdx.x; i < n4; i += stride) {
        float4 v = ((const float4*)s)[i];
        uint2 H, L;
        H.x = packh2_split(v.x, v.y, L.x);
        H.y = packh2_split(v.z, v.w, L.y);
        ((uint2*)h)[i] = H;
        ((uint2*)l)[i] = L;
    }
}
// hi-only convert (lm_head weights)
__global__ void conv_kernel(const float* __restrict__ s,
                            __half* __restrict__ h, long n4)
{
    long stride = (long)gridDim.x * blockDim.x;
    for (long i = (long)blockIdx.x * blockDim.x + threadIdx.x; i < n4; i += stride) {
        float4 v = ((const float4*)s)[i];
        uint2 H;
        H.x = packh2(v.x, v.y);
        H.y = packh2(v.z, v.w);
        ((uint2*)h)[i] = H;
    }
}

// ---------------- embedding ----------------
__global__ void embed_kernel(const int* __restrict__ idx,
                             const float* __restrict__ wte,
                             const float* __restrict__ wpe,
                             float* __restrict__ x)
{
    int m = blockIdx.x;
    int t = m & (TT-1);
    int tok = idx[m];
    const float* we = wte + (size_t)tok * CC;
    const float* wp = wpe + (size_t)t * CC;
    float* xr = x + (size_t)m * CC;
    for (int c = threadIdx.x; c < CC; c += blockDim.x)
        xr[c] = we[c] + wp[c];
}

// ---------------- layernorm -> fp16 ----------
__global__ void ln_kernel(const float* __restrict__ x,
                          const float* __restrict__ w,
                          const float* __restrict__ b,
                          __half* __restrict__ yh)
{
    __shared__ float red[16];
    int row  = blockIdx.x;
    int tid  = threadIdx.x;
    int lane = tid & 31;
    int warp = tid >> 5;
    const float* xr = x + (size_t)row * CC;

    float v0 = xr[tid], v1 = xr[tid+256], v2 = xr[tid+512];
    float s = v0 + v1 + v2;
    #pragma unroll
    for (int o = 16; o; o >>= 1) s += __shfl_xor_sync(0xffffffffu, s, o);
    if (!lane) red[warp] = s;
    __syncthreads();
    float mu = (red[0]+red[1]+red[2]+red[3]+red[4]+red[5]+red[6]+red[7]) * (1.0f/CC);

    float d0 = v0-mu, d1 = v1-mu, d2 = v2-mu;
    float q = d0*d0 + d1*d1 + d2*d2;
    #pragma unroll
    for (int o = 16; o; o >>= 1) q += __shfl_xor_sync(0xffffffffu, q, o);
    if (!lane) red[8+warp] = q;
    __syncthreads();
    float rstd = rsqrtf((red[8]+red[9]+red[10]+red[11]+red[12]+red[13]+red[14]+red[15])
                        * (1.0f/CC) + 1e-5f);

    size_t base = (size_t)row * CC;
    #pragma unroll
    for (int j = 0; j < 3; j++) {
        int c = tid + j*256;
        float v = (j==0?d0:(j==1?d1:d2))*rstd*w[c] + b[c];
        yh[base+c] = __float2half(v);
    }
}

// ---------------- fp16 HMMA GEMM, 128x128 tile, 1- or 2-term weights ----------
// Y = X @ W^T (+bias)(gelu)(+res). X fp16, W fp16 hi(+lo).
// 8 warps (2x4); warp tile 64x32. BK=32, 3-stage cp.async pipeline.
#define BKG 32

template<bool TWOTERM, bool GELU, bool RES, bool OUTHALF>
__global__ void __launch_bounds__(256)
gemm_hmma(const __half* __restrict__ X,
          const __half* __restrict__ Wh, const __half* __restrict__ Wl,
          const float* __restrict__ bias, const float* __restrict__ res,
          float* __restrict__ Y, __half* __restrict__ Yh,
          int M, int N, int K)
{
    constexpr int ATILE  = 8192;                    // A tile bytes (128 rows x 64B)
    constexpr int BTILE  = 8192;
    constexpr int STAGEB = ATILE + (TWOTERM ? 2 : 1) * BTILE;

    extern __shared__ char sm[];
    const uint32_t sb = smem_u32(sm);

    const int tid  = threadIdx.x;
    const int lane = tid & 31;
    const int warp = tid >> 5;
    const int wm   = warp & 1;
    const int wn   = warp >> 1;
    const int g    = lane >> 2;
    const int tg   = lane & 3;
    const int bm   = blockIdx.x * 128;
    const int bn   = blockIdx.y * 128;

    float d[4][4][4];
    #pragma unroll
    for (int i = 0; i < 4; i++)
        #pragma unroll
        for (int j = 0; j < 4; j++) {
            d[i][j][0]=0.f; d[i][j][1]=0.f; d[i][j][2]=0.f; d[i][j][3]=0.f;
        }

    // ---- global->smem mapping: thread covers row lr, chunks {lcb, lcb+1} ----
    const int lr  = tid >> 1;
    const int lcb = (tid & 1) * 2;
    const __half* x_p  = X  + (size_t)(bm + lr)*K;
    const __half* wh_p = Wh + (size_t)(bn + lr)*K;
    const __half* wl_p = TWOTERM ? (Wl + (size_t)(bn + lr)*K) : nullptr;
    const int rsw = (lr >> 1) & 3;
    uint32_t so[2];
    #pragma unroll
    for (int i = 0; i < 2; i++)
        so[i] = (uint32_t)(lr*64 + (((lcb+i) ^ rsw) << 4));

    // ---- ldmatrix fragment addresses ----
    uint32_t a_off[4][2], b_off[2][2];
    {
        int arow = wm*64 + (lane & 15);
        int ln16 = lane >> 4;
        #pragma unroll
        for (int fm = 0; fm < 4; fm++) {
            int r = arow + fm*16;
            #pragma unroll
            for (int ks = 0; ks < 2; ks++) {
                int c = ks*2 + ln16;
                a_off[fm][ks] = (uint32_t)(r*64 + ((c ^ ((r>>1)&3)) << 4));
            }
        }
        int q = lane >> 3;
        int brow = wn*32 + ((q >> 1) << 3) + (lane & 7);
        int cadd = q & 1;
        #pragma unroll
        for (int fnp = 0; fnp < 2; fnp++) {
            int r = brow + fnp*16;
            #pragma unroll
            for (int ks = 0; ks < 2; ks++) {
                int c = ks*2 + cadd;
                b_off[fnp][ks] = (uint32_t)(r*64 + ((c ^ ((r>>1)&3)) << 4));
            }
        }
    }

    const int NT = K / BKG;

    auto issue_stage = [&](int stage, uint32_t base) {
        const int k0 = stage * BKG;
        #pragma unroll
        for (int i = 0; i < 2; i++) {
            int c = lcb + i;
            cpasync16(base +          so[i], (const char*)(x_p  + k0) + c*16);
            cpasync16(base + ATILE +  so[i], (const char*)(wh_p + k0) + c*16);
            if (TWOTERM)
                cpasync16(base + ATILE + BTILE + so[i], (const char*)(wl_p + k0) + c*16);
        }
    };

    #pragma unroll
    for (int s = 0; s < 2; s++) {
        issue_stage(s, sb + (uint32_t)s * STAGEB);
        cp_commit();
    }

    int bufc = 0;
    for (int t = 0; t < NT; t++) {
        cp_wait<1>();
        __syncthreads();

        if (t + 2 < NT) {
            int bufs = bufc + 2; if (bufs >= 3) bufs -= 3;
            issue_stage(t + 2, sb + (uint32_t)bufs * STAGEB);
        }
        cp_commit();

        {
            uint32_t base = sb + (uint32_t)bufc * STAGEB;
            uint32_t aX = base;
            uint32_t bH = base + ATILE, bL = base + ATILE + BTILE;

            #pragma unroll
            for (int ks = 0; ks < 2; ks++) {
                uint32_t ah[4][4], bh[4][2], bl[4][2];
                #pragma unroll
                for (int fm = 0; fm < 4; fm++)
                    ldsm4(ah[fm][0], ah[fm][1], ah[fm][2], ah[fm][3], aX + a_off[fm][ks]);
                #pragma unroll
                for (int fnp = 0; fnp < 2; fnp++) {
                    uint32_t r0, r1, r2, r3;
                    ldsm4(r0, r1, r2, r3, bH + b_off[fnp][ks]);
                    bh[fnp*2][0]=r0; bh[fnp*2][1]=r1; bh[fnp*2+1][0]=r2; bh[fnp*2+1][1]=r3;
                    if (TWOTERM) {
                        ldsm4(r0, r1, r2, r3, bL + b_off[fnp][ks]);
                        bl[fnp*2][0]=r0; bl[fnp*2][1]=r1; bl[fnp*2+1][0]=r2; bl[fnp*2+1][1]=r3;
                    }
                }
                #pragma unroll
                for (int fm = 0; fm < 4; fm++)
                    #pragma unroll
                    for (int fn = 0; fn < 4; fn++) {
                        mma16816h(d[fm][fn], ah[fm][0],ah[fm][1],ah[fm][2],ah[fm][3],
                                  bh[fn][0], bh[fn][1]);
                        if (TWOTERM)
                            mma16816h(d[fm][fn], ah[fm][0],ah[fm][1],ah[fm][2],ah[fm][3],
                                      bl[fn][0], bl[fn][1]);
                    }
            }
        }
        bufc = (bufc + 1 == 3) ? 0 : bufc + 1;
    }

    #pragma unroll
    for (int fm = 0; fm < 4; fm++) {
        int mrow = bm + wm*64 + fm*16 + g;
        #pragma unroll
        for (int half = 0; half < 2; half++) {
            int m = mrow + half*8;
            #pragma unroll
            for (int fn = 0; fn < 4; fn++) {
                int n0 = bn + wn*32 + fn*8 + tg*2;
                float v0 = d[fm][fn][half*2+0];
                float v1 = d[fm][fn][half*2+1];
                if (bias) { v0 += bias[n0]; v1 += bias[n0+1]; }
                if (GELU) { v0 = gelu_tanh(v0); v1 = gelu_tanh(v1); }
                if (RES) {
                    float2 rv = *(const float2*)&res[(size_t)m*N + n0];
                    v0 += rv.x; v1 += rv.y;
                }
                if (OUTHALF) {
                    *(uint32_t*)&Yh[(size_t)m*N + n0] = packh2(v0, v1);
                } else {
                    float2 o2; o2.x = v0; o2.y = v1;
                    *(float2*)&Y[(size_t)m*N + n0] = o2;
                }
            }
        }
    }
}

// smem sizes per instantiation
#define SM128_2 (3*(8192 + 2*8192))   // 73728
#define SM128_1 (3*(8192 + 1*8192))   // 49152

// ---------------- tensor-core flash attention (bf16 3-term, fp16 output) ----
__global__ void __launch_bounds__(256)
attn_tc(const float* __restrict__ qkv, __half* __restrict__ yh)
{
    __shared__ char smem[32768];
    const uint32_t sb = smem_u32(smem);
    const int tid  = threadIdx.x;
    const int lane = tid & 31;
    const int w    = tid >> 5;
    const int g    = lane >> 2;
    const int tg   = lane & 3;
    const int qt   = gridDim.x - 1 - blockIdx.x;
    const int h    = blockIdx.y;
    const int b    = blockIdx.z;
    const int q0   = qt * 128;

    const float SC = 0.18033688011112042f;   // 0.125 * log2(e)

    {
        int r  = tid >> 1;
        int dh = (tid & 1) * 32;
        const float* src = qkv + (size_t)(b*TT + q0 + r)*C3 + h*DD + dh;
        #pragma unroll
        for (int cc = 0; cc < 4; cc++) {
            float4 v0 = *(const float4*)(src + cc*8);
            float4 v1 = *(const float4*)(src + cc*8 + 4);
            uint4 Hc, Lc;
            Hc.x = pack2(v0.x*SC, v0.y*SC, Lc.x);
            Hc.y = pack2(v0.z*SC, v0.w*SC, Lc.y);
            Hc.z = pack2(v1.x*SC, v1.y*SC, Lc.z);
            Hc.w = pack2(v1.z*SC, v1.w*SC, Lc.w);
            int c = (dh >> 3) + cc;
            uint32_t off = (uint32_t)(r*128 + ((c ^ (r & 7)) << 4));
            *(uint4*)(smem + off)         = Hc;
            *(uint4*)(smem + 16384 + off) = Lc;
        }
    }
    __syncthreads();

    uint32_t qh[4][4], ql[4][4];
    #pragma unroll
    for (int kk = 0; kk < 4; kk++) {
        int row = w*16 + (lane & 15);
        int c   = kk*2 + (lane >> 4);
        uint32_t off = (uint32_t)(row*128 + ((c ^ (row & 7)) << 4));
        ldsm4(qh[kk][0], qh[kk][1], qh[kk][2], qh[kk][3], sb + off);
        ldsm4(ql[kk][0], ql[kk][1], ql[kk][2], ql[kk][3], sb + 16384 + off);
    }

    float o[8][4];
    #pragma unroll
    for (int j = 0; j < 8; j++) { o[j][0]=0.f; o[j][1]=0.f; o[j][2]=0.f; o[j][3]=0.f; }
    float mrow0 = -1e30f, mrow1 = -1e30f, lrow0 = 0.f, lrow1 = 0.f;

    const int qrow0 = q0 + w*16 + g;
    const int nk  = (q0 + 128) >> 6;
    const int nkw = ((q0 + w*16 + 15) >> 6) + 1;

    const uint32_t KH_ = 0u, KL_ = 8192u, VH_ = 16384u, VL_ = 24576u;

    for (int kt = 0; kt < nk; kt++) {
        __syncthreads();

        {
            int r  = tid >> 2;
            int dq = (tid & 3) * 16;
            const float* kr = qkv + (size_t)(b*TT + kt*64 + r)*C3 + CC + h*DD + dq;
            const float* vr = kr + CC;
            #pragma unroll
            for (int half = 0; half < 2; half++) {
                int c = (dq >> 3) + half;
                uint32_t off = (uint32_t)(r*128 + ((c ^ (r & 7)) << 4));
                float4 k0 = *(const float4*)(kr + half*8);
                float4 k1 = *(const float4*)(kr + half*8 + 4);
                uint4 Hc, Lc;
                Hc.x = pack2(k0.x, k0.y, Lc.x);
                Hc.y = pack2(k0.z, k0.w, Lc.y);
                Hc.z = pack2(k1.x, k1.y, Lc.z);
                Hc.w = pack2(k1.z, k1.w, Lc.w);
                *(uint4*)(smem + KH_ + off) = Hc;
                *(uint4*)(smem + KL_ + off) = Lc;
                float4 w0 = *(const float4*)(vr + half*8);
                float4 w1 = *(const float4*)(vr + half*8 + 4);
                Hc.x = pack2(w0.x, w0.y, Lc.x);
                Hc.y = pack2(w0.z, w0.w, Lc.y);
                Hc.z = pack2(w1.x, w1.y, Lc.z);
                Hc.w = pack2(w1.z, w1.w, Lc.w);
                *(uint4*)(smem + VH_ + off) = Hc;
                *(uint4*)(smem + VL_ + off) = Lc;
            }
        }
        __syncthreads();

        if (kt >= nkw) continue;

        float s[8][4];
        #pragma unroll
        for (int j = 0; j < 8; j++) { s[j][0]=0.f; s[j][1]=0.f; s[j][2]=0.f; s[j][3]=0.f; }

        #pragma unroll
        for (int kk = 0; kk < 4; kk++) {
            int q4 = lane >> 3;
            #pragma unroll
            for (int jj = 0; jj < 4; jj++) {
                int row = jj*16 + ((q4 >> 1) << 3) + (lane & 7);
                int c   = kk*2 + (q4 & 1);
                uint32_t off = (uint32_t)(row*128 + ((c ^ (row & 7)) << 4));
                uint32_t h0,h1,h2,h3, l0,l1,l2,l3;
                ldsm4(h0, h1, h2, h3, sb + KH_ + off);
                ldsm4(l0, l1, l2, l3, sb + KL_ + off);
                mma16816(s[2*jj  ], qh[kk][0],qh[kk][1],qh[kk][2],qh[kk][3], h0, h1);
                mma16816(s[2*jj  ], ql[kk][0],ql[kk][1],ql[kk][2],ql[kk][3], h0, h1);
                mma16816(s[2*jj  ], qh[kk][0],qh[kk][1],qh[kk][2],qh[kk][3], l0, l1);
                mma16816(s[2*jj+1], qh[kk][0],qh[kk][1],qh[kk][2],qh[kk][3], h2, h3);
                mma16816(s[2*jj+1], ql[kk][0],ql[kk][1],ql[kk][2],ql[kk][3], h2, h3);
                mma16816(s[2*jj+1], qh[kk][0],qh[kk][1],qh[kk][2],qh[kk][3], l2, l3);
            }
        }

        if (kt*64 + 63 > q0 + w*16) {
            #pragma unroll
            for (int j = 0; j < 8; j++) {
                int c0 = kt*64 + j*8 + 2*tg;
                if (c0     > qrow0)     s[j][0] = -1e30f;
                if (c0 + 1 > qrow0)     s[j][1] = -1e30f;
                if (c0     > qrow0 + 8) s[j][2] = -1e30f;
                if (c0 + 1 > qrow0 + 8) s[j][3] = -1e30f;
            }
        }

        float mx0 = -1e30f, mx1 = -1e30f;
        #pragma unroll
        for (int j = 0; j < 8; j++) {
            mx0 = fmaxf(mx0, fmaxf(s[j][0], s[j][1]));
            mx1 = fmaxf(mx1, fmaxf(s[j][2], s[j][3]));
        }
        mx0 = fmaxf(mx0, __shfl_xor_sync(0xffffffffu, mx0, 1));
        mx0 = fmaxf(mx0, __shfl_xor_sync(0xffffffffu, mx0, 2));
        mx1 = fmaxf(mx1, __shfl_xor_sync(0xffffffffu, mx1, 1));
        mx1 = fmaxf(mx1, __shfl_xor_sync(0xffffffffu, mx1, 2));

        float mn0 = fmaxf(mrow0, mx0), mn1 = fmaxf(mrow1, mx1);
        float a0  = ex2f(mrow0 - mn0), a1  = ex2f(mrow1 - mn1);
        float ls0 = 0.f, ls1 = 0.f;
        #pragma unroll
        for (int j = 0; j < 8; j++) {
            s[j][0] = ex2f(s[j][0] - mn0);  ls0 += s[j][0];
            s[j][1] = ex2f(s[j][1] - mn0);  ls0 += s[j][1];
            s[j][2] = ex2f(s[j][2] - mn1);  ls1 += s[j][2];
            s[j][3] = ex2f(s[j][3] - mn1);  ls1 += s[j][3];
        }
        ls0 += __shfl_xor_sync(0xffffffffu, ls0, 1);
        ls0 += __shfl_xor_sync(0xffffffffu, ls0, 2);
        ls1 += __shfl_xor_sync(0xffffffffu, ls1, 1);
        ls1 += __shfl_xor_sync(0xffffffffu, ls1, 2);
        lrow0 = lrow0*a0 + ls0;  lrow1 = lrow1*a1 + ls1;
        mrow0 = mn0;  mrow1 = mn1;
        #pragma unroll
        for (int j = 0; j < 8; j++) {
            o[j][0] *= a0; o[j][1] *= a0; o[j][2] *= a1; o[j][3] *= a1;
        }

        uint32_t* sp = (uint32_t*)s;
        #pragma unroll
        for (int kk = 0; kk < 4; kk++) {
            uint32_t lo;
            uint32_t h0 = pack2(s[2*kk][0],   s[2*kk][1],   lo);
            sp[kk*8+0] = h0; sp[kk*8+1] = lo;
            uint32_t h1 = pack2(s[2*kk][2],   s[2*kk][3],   lo);
            sp[kk*8+2] = h1; sp[kk*8+3] = lo;
            uint32_t h2 = pack2(s[2*kk+1][0], s[2*kk+1][1], lo);
            sp[kk*8+4] = h2; sp[kk*8+5] = lo;
            uint32_t h3 = pack2(s[2*kk+1][2], s[2*kk+1][3], lo);
            sp[kk*8+6] = h3; sp[kk*8+7] = lo;
        }

        #pragma unroll
        for (int kk = 0; kk < 4; kk++) {
            uint32_t pa0 = sp[kk*8+0], pa1 = sp[kk*8+2], pa2 = sp[kk*8+4], pa3 = sp[kk*8+6];
            uint32_t pb0 = sp[kk*8+1], pb1 = sp[kk*8+3], pb2 = sp[kk*8+5], pb3 = sp[kk*8+7];
            int tl = lane >> 3;
            #pragma unroll
            for (int jj = 0; jj < 4; jj++) {
                int row = kk*16 + ((tl & 1) << 3) + (lane & 7);
                int c   = jj*2 + (tl >> 1);
                uint32_t off = (uint32_t)(row*128 + ((c ^ (row & 7)) << 4));
                uint32_t v0,v1,v2,v3, u0,u1,u2,u3;
                ldsm4t(v0, v1, v2, v3, sb + VH_ + off);
                ldsm4t(u0, u1, u2, u3, sb + VL_ + off);
                mma16816(o[2*jj  ], pa0, pa1, pa2, pa3, v0, v1);
                mma16816(o[2*jj  ], pb0, pb1, pb2, pb3, v0, v1);
                mma16816(o[2*jj  ], pa0, pa1, pa2, pa3, u0, u1);
                mma16816(o[2*jj+1], pa0, pa1, pa2, pa3, v2, v3);
                mma16816(o[2*jj+1], pb0, pb1, pb2, pb3, v2, v3);
                mma16816(o[2*jj+1], pa0, pa1, pa2, pa3, u2, u3);
            }
        }
    }

    float inv0 = 1.0f / lrow0, inv1 = 1.0f / lrow1;
    #pragma unroll
    for (int j = 0; j < 8; j++) {
        size_t oidx = (size_t)(b*TT + qrow0)*CC + h*DD + j*8 + 2*tg;
        *(uint32_t*)&yh[oidx] = packh2(o[j][0]*inv0, o[j][1]*inv0);
        oidx += (size_t)8*CC;
        *(uint32_t*)&yh[oidx] = packh2(o[j][2]*inv1, o[j][3]*inv1);
    }
}

// ---------------- launch ----------------
extern "C" void kernel_launch(void* const* d_in, const int* in_sizes, int n_in,
                              void* d_out, int out_size)
{
    (void)in_sizes; (void)n_in; (void)out_size;
    const int*   idx     = (const int*)  d_in[0];
    const float* wte     = (const float*)d_in[1];
    const float* wpe     = (const float*)d_in[2];
    const float* ln1w    = (const float*)d_in[3];
    const float* ln1b    = (const float*)d_in[4];
    const float* qkvw    = (const float*)d_in[5];
    const float* qkvb    = (const float*)d_in[6];
    const float* projw   = (const float*)d_in[7];
    const float* projb   = (const float*)d_in[8];
    const float* ln2w    = (const float*)d_in[9];
    const float* ln2b    = (const float*)d_in[10];
    const float* fcw     = (const float*)d_in[11];
    const float* fcb     = (const float*)d_in[12];
    const float* fcprojw = (const float*)d_in[13];
    const float* fcprojb = (const float*)d_in[14];
    const float* lnfw    = (const float*)d_in[15];
    const float* lnfb    = (const float*)d_in[16];
    float* out = (float*)d_out;

    float *x, *qkv;
    __half *ln, *att, *act;
    __half *qkvwh, *qkvwl, *projwh, *projwl, *fcwh, *fcwl, *fcpwh, *fcpwl, *wteh;
    cudaGetSymbolAddress((void**)&x,    g_x);
    cudaGetSymbolAddress((void**)&qkv,  g_qkv);
    cudaGetSymbolAddress((void**)&ln,   g_ln);
    cudaGetSymbolAddress((void**)&att,  g_att);
    cudaGetSymbolAddress((void**)&act,  g_act);
    cudaGetSymbolAddress((void**)&qkvwh, g_qkvw_h); cudaGetSymbolAddress((void**)&qkvwl, g_qkvw_l);
    cudaGetSymbolAddress((void**)&projwh,g_projw_h);cudaGetSymbolAddress((void**)&projwl,g_projw_l);
    cudaGetSymbolAddress((void**)&fcwh, g_fcw_h);  cudaGetSymbolAddress((void**)&fcwl, g_fcw_l);
    cudaGetSymbolAddress((void**)&fcpwh,g_fcpw_h); cudaGetSymbolAddress((void**)&fcpwl,g_fcpw_l);
    cudaGetSymbolAddress((void**)&wteh, g_wte_h);

    cudaFuncSetAttribute(gemm_hmma<true ,false,false,false>, cudaFuncAttributeMaxDynamicSharedMemorySize, SM128_2);
    cudaFuncSetAttribute(gemm_hmma<true ,false,true ,false>, cudaFuncAttributeMaxDynamicSharedMemorySize, SM128_2);
    cudaFuncSetAttribute(gemm_hmma<true ,true ,false,true >, cudaFuncAttributeMaxDynamicSharedMemorySize, SM128_2);
    cudaFuncSetAttribute(gemm_hmma<false,false,false,false>, cudaFuncAttributeMaxDynamicSharedMemorySize, SM128_1);

    const int SB = 1184;
    split_kernel<<<SB, 256>>>(qkvw,    qkvwh,  qkvwl,  (long)LL*C3*CC/4);
    split_kernel<<<SB, 256>>>(projw,   projwh, projwl, (long)LL*CC*CC/4);
    split_kernel<<<SB, 256>>>(fcw,     fcwh,   fcwl,   (long)LL*C4*CC/4);
    split_kernel<<<SB, 256>>>(fcprojw, fcpwh,  fcpwl,  (long)LL*CC*C4/4);
    conv_kernel <<<SB, 256>>>(wte,     wteh,           (long)VP*CC/4);

    embed_kernel<<<MROWS, 256>>>(idx, wte, wpe, x);

    for (int l = 0; l < LL; l++) {
        ln_kernel<<<MROWS, 256>>>(x, ln1w + l*CC, ln1b + l*CC, ln);

        gemm_hmma<true,false,false,false><<<dim3(MROWS/128, C3/128), 256, SM128_2>>>(
            ln, qkvwh + (size_t)l*C3*CC, qkvwl + (size_t)l*C3*CC,
            qkvb + (size_t)l*C3, nullptr, qkv, nullptr, MROWS, C3, CC);

        attn_tc<<<dim3(TT/128, HH, BATCH), 256>>>(qkv, att);

        gemm_hmma<true,false,true,false><<<dim3(MROWS/128, CC/128), 256, SM128_2>>>(
            att, projwh + (size_t)l*CC*CC, projwl + (size_t)l*CC*CC,
            projb + (size_t)l*CC, x, x, nullptr, MROWS, CC, CC);

        ln_kernel<<<MROWS, 256>>>(x, ln2w + l*CC, ln2b + l*CC, ln);

        gemm_hmma<true,true,false,true><<<dim3(MROWS/128, C4/128), 256, SM128_2>>>(
            ln, fcwh + (size_t)l*C4*CC, fcwl + (size_t)l*C4*CC,
            fcb + (size_t)l*C4, nullptr, nullptr, act, MROWS, C4, CC);

        gemm_hmma<true,false,true,false><<<dim3(MROWS/128, CC/128), 256, SM128_2>>>(
            act, fcpwh + (size_t)l*CC*C4, fcpwl + (size_t)l*CC*C4,
            fcprojb + (size_t)l*CC, x, x, nullptr, MROWS, CC, C4);
    }

    ln_kernel<<<MROWS, 256>>>(x, lnfw, lnfb, ln);

    gemm_hmma<false,false,false,false><<<dim3(MROWS/128, VP/128), 256, SM128_1>>>(
        ln, wteh, nullptr, nullptr, nullptr, out, nullptr, MROWS, VP, CC);
}

// round 12
// speedup vs baseline: 1.4125x; 1.2910x over previous
#include <cuda_runtime.h>
#include <cuda_bf16.h>
#include <cuda_fp16.h>
#include <math.h>
#include <stdint.h>

// ---------------- problem constants ----------------
#define BATCH 2
#define TT    1024
#define CC    768
#define HH    12
#define DD    64
#define LL    12
#define MROWS (BATCH*TT)      // 2048
#define C3    (3*CC)          // 2304
#define C4    (4*CC)          // 3072
#define VP    50304

// ---------------- scratch (device globals) ----------
__device__ float g_x  [MROWS*CC];
__device__ float g_qkv[MROWS*C3];

__device__ __half g_ln [MROWS*CC];
__device__ __half g_att[MROWS*CC];
__device__ __half g_act[MROWS*C4];

// fp16 weights (hi only — weight-lo term dropped this round)
__device__ __half g_qkvw_h [(size_t)LL*C3*CC];
__device__ __half g_projw_h[(size_t)LL*CC*CC];
__device__ __half g_fcw_h  [(size_t)LL*C4*CC];
__device__ __half g_fcpw_h [(size_t)LL*CC*C4];
__device__ __half g_wte_h  [(size_t)VP*CC];

// ---------------- small helpers ----------------
__device__ __forceinline__ uint32_t pack2(float x, float y, uint32_t &lo)
{
    __nv_bfloat16 xh = __float2bfloat16(x);
    __nv_bfloat16 yh = __float2bfloat16(y);
    __nv_bfloat162 H; H.x = xh; H.y = yh;
    __nv_bfloat162 L; L.x = __float2bfloat16(x - __bfloat162float(xh));
    L.y = __float2bfloat16(y - __bfloat162float(yh));
    lo = *reinterpret_cast<const uint32_t*>(&L);
    return *reinterpret_cast<const uint32_t*>(&H);
}
__device__ __forceinline__ uint32_t packh2(float x, float y)
{
    __half2 H; H.x = __float2half(x); H.y = __float2half(y);
    return *reinterpret_cast<const uint32_t*>(&H);
}

__device__ __forceinline__ float gelu_tanh(float x) {
    float x3 = x*x*x;
    return 0.5f * x * (1.0f + tanhf(0.7978845608028654f * (x + 0.044715f * x3)));
}

__device__ __forceinline__ float ex2f(float x) {
    float y;
    asm("ex2.approx.f32 %0, %1;" : "=f"(y) : "f"(x));
    return y;
}

__device__ __forceinline__ uint32_t smem_u32(const void* p) {
    uint32_t a;
    asm("{ .reg .u64 t; cvta.to.shared.u64 t, %1; cvt.u32.u64 %0, t; }"
        : "=r"(a) : "l"(p));
    return a;
}
__device__ __forceinline__ void cpasync16(uint32_t dst, const void* src) {
    asm volatile("cp.async.cg.shared.global [%0], [%1], 16;"
                 :: "r"(dst), "l"(__cvta_generic_to_global(src)));
}
__device__ __forceinline__ void cp_commit() {
    asm volatile("cp.async.commit_group;");
}
template<int N>
__device__ __forceinline__ void cp_wait() {
    asm volatile("cp.async.wait_group %0;" :: "n"(N));
}
__device__ __forceinline__ void ldsm4(uint32_t& r0, uint32_t& r1,
                                      uint32_t& r2, uint32_t& r3, uint32_t addr) {
    asm volatile("ldmatrix.sync.aligned.m8n8.x4.shared.b16 {%0,%1,%2,%3}, [%4];"
                 : "=r"(r0), "=r"(r1), "=r"(r2), "=r"(r3) : "r"(addr));
}
__device__ __forceinline__ void ldsm4t(uint32_t& r0, uint32_t& r1,
                                       uint32_t& r2, uint32_t& r3, uint32_t addr) {
    asm volatile("ldmatrix.sync.aligned.m8n8.x4.trans.shared.b16 {%0,%1,%2,%3}, [%4];"
                 : "=r"(r0), "=r"(r1), "=r"(r2), "=r"(r3) : "r"(addr));
}
__device__ __forceinline__ void mma16816(float* d,
    uint32_t a0, uint32_t a1, uint32_t a2, uint32_t a3,
    uint32_t b0, uint32_t b1)
{
    asm volatile(
        "mma.sync.aligned.m16n8k16.row.col.f32.bf16.bf16.f32 "
        "{%0,%1,%2,%3}, {%4,%5,%6,%7}, {%8,%9}, {%0,%1,%2,%3};"
        : "+f"(d[0]), "+f"(d[1]), "+f"(d[2]), "+f"(d[3])
        : "r"(a0), "r"(a1), "r"(a2), "r"(a3), "r"(b0), "r"(b1));
}
__device__ __forceinline__ void mma16816h(float* d,
    uint32_t a0, uint32_t a1, uint32_t a2, uint32_t a3,
    uint32_t b0, uint32_t b1)
{
    asm volatile(
        "mma.sync.aligned.m16n8k16.row.col.f32.f16.f16.f32 "
        "{%0,%1,%2,%3}, {%4,%5,%6,%7}, {%8,%9}, {%0,%1,%2,%3};"
        : "+f"(d[0]), "+f"(d[1]), "+f"(d[2]), "+f"(d[3])
        : "r"(a0), "r"(a1), "r"(a2), "r"(a3), "r"(b0), "r"(b1));
}

// ---------------- weight convert fp32 -> fp16 ----------------
__global__ void conv_kernel(const float* __restrict__ s,
                            __half* __restrict__ h, long n4)
{
    long stride = (long)gridDim.x * blockDim.x;
    for (long i = (long)blockIdx.x * blockDim.x + threadIdx.x; i < n4; i += stride) {
        float4 v = ((const float4*)s)[i];
        uint2 H;
        H.x = packh2(v.x, v.y);
        H.y = packh2(v.z, v.w);
        ((uint2*)h)[i] = H;
    }
}

// ---------------- embedding ----------------
__global__ void embed_kernel(const int* __restrict__ idx,
                             const float* __restrict__ wte,
                             const float* __restrict__ wpe,
                             float* __restrict__ x)
{
    int m = blockIdx.x;
    int t = m & (TT-1);
    int tok = idx[m];
    const float* we = wte + (size_t)tok * CC;
    const float* wp = wpe + (size_t)t * CC;
    float* xr = x + (size_t)m * CC;
    for (int c = threadIdx.x; c < CC; c += blockDim.x)
        xr[c] = we[c] + wp[c];
}

// ---------------- layernorm -> fp16 ----------
__global__ void ln_kernel(const float* __restrict__ x,
                          const float* __restrict__ w,
                          const float* __restrict__ b,
                          __half* __restrict__ yh)
{
    __shared__ float red[16];
    int row  = blockIdx.x;
    int tid  = threadIdx.x;
    int lane = tid & 31;
    int warp = tid >> 5;
    const float* xr = x + (size_t)row * CC;

    float v0 = xr[tid], v1 = xr[tid+256], v2 = xr[tid+512];
    float s = v0 + v1 + v2;
    #pragma unroll
    for (int o = 16; o; o >>= 1) s += __shfl_xor_sync(0xffffffffu, s, o);
    if (!lane) red[warp] = s;
    __syncthreads();
    float mu = (red[0]+red[1]+red[2]+red[3]+red[4]+red[5]+red[6]+red[7]) * (1.0f/CC);

    float d0 = v0-mu, d1 = v1-mu, d2 = v2-mu;
    float q = d0*d0 + d1*d1 + d2*d2;
    #pragma unroll
    for (int o = 16; o; o >>= 1) q += __shfl_xor_sync(0xffffffffu, q, o);
    if (!lane) red[8+warp] = q;
    __syncthreads();
    float rstd = rsqrtf((red[8]+red[9]+red[10]+red[11]+red[12]+red[13]+red[14]+red[15])
                        * (1.0f/CC) + 1e-5f);

    size_t base = (size_t)row * CC;
    #pragma unroll
    for (int j = 0; j < 3; j++) {
        int c = tid + j*256;
        float v = (j==0?d0:(j==1?d1:d2))*rstd*w[c] + b[c];
        yh[base+c] = __float2half(v);
    }
}

// ---------------- fp16 HMMA GEMM, 128x128 tile, single-term ----------
// Y = X @ W^T (+bias)(gelu)(+res). X, W fp16.
// 8 warps (2x4); warp tile 64x32. BK=32, 3-stage cp.async pipeline.
#define BKG 32
#define ATILE  8192
#define BTILE  8192
#define STAGEB (ATILE + BTILE)     // 16KB
#define GSMEM  (3*STAGEB)          // 49152

template<bool GELU, bool RES, bool OUTHALF>
__global__ void __launch_bounds__(256)
gemm_hmma(const __half* __restrict__ X, const __half* __restrict__ Wh,
          const float* __restrict__ bias, const float* __restrict__ res,
          float* __restrict__ Y, __half* __restrict__ Yh,
          int M, int N, int K)
{
    extern __shared__ char sm[];
    const uint32_t sb = smem_u32(sm);

    const int tid  = threadIdx.x;
    const int lane = tid & 31;
    const int warp = tid >> 5;
    const int wm   = warp & 1;
    const int wn   = warp >> 1;
    const int g    = lane >> 2;
    const int tg   = lane & 3;
    const int bm   = blockIdx.x * 128;
    const int bn   = blockIdx.y * 128;

    float d[4][4][4];
    #pragma unroll
    for (int i = 0; i < 4; i++)
        #pragma unroll
        for (int j = 0; j < 4; j++) {
            d[i][j][0]=0.f; d[i][j][1]=0.f; d[i][j][2]=0.f; d[i][j][3]=0.f;
        }

    // ---- global->smem mapping: thread covers row lr, chunks {lcb, lcb+1} ----
    const int lr  = tid >> 1;
    const int lcb = (tid & 1) * 2;
    const __half* x_p  = X  + (size_t)(bm + lr)*K;
    const __half* wh_p = Wh + (size_t)(bn + lr)*K;
    const int rsw = (lr >> 1) & 3;
    uint32_t so[2];
    #pragma unroll
    for (int i = 0; i < 2; i++)
        so[i] = (uint32_t)(lr*64 + (((lcb+i) ^ rsw) << 4));

    // ---- ldmatrix fragment addresses ----
    uint32_t a_off[4][2], b_off[2][2];
    {
        int arow = wm*64 + (lane & 15);
        int ln16 = lane >> 4;
        #pragma unroll
        for (int fm = 0; fm < 4; fm++) {
            int r = arow + fm*16;
            #pragma unroll
            for (int ks = 0; ks < 2; ks++) {
                int c = ks*2 + ln16;
                a_off[fm][ks] = (uint32_t)(r*64 + ((c ^ ((r>>1)&3)) << 4));
            }
        }
        int q = lane >> 3;
        int brow = wn*32 + ((q >> 1) << 3) + (lane & 7);
        int cadd = q & 1;
        #pragma unroll
        for (int fnp = 0; fnp < 2; fnp++) {
            int r = brow + fnp*16;
            #pragma unroll
            for (int ks = 0; ks < 2; ks++) {
                int c = ks*2 + cadd;
                b_off[fnp][ks] = (uint32_t)(r*64 + ((c ^ ((r>>1)&3)) << 4));
            }
        }
    }

    const int NT = K / BKG;

    auto issue_stage = [&](int stage, uint32_t base) {
        const int k0 = stage * BKG;
        #pragma unroll
        for (int i = 0; i < 2; i++) {
            int c = lcb + i;
            cpasync16(base +          so[i], (const char*)(x_p  + k0) + c*16);
            cpasync16(base + ATILE +  so[i], (const char*)(wh_p + k0) + c*16);
        }
    };

    #pragma unroll
    for (int s = 0; s < 2; s++) {
        issue_stage(s, sb + (uint32_t)s * STAGEB);
        cp_commit();
    }

    int bufc = 0;
    for (int t = 0; t < NT; t++) {
        cp_wait<1>();
        __syncthreads();

        if (t + 2 < NT) {
            int bufs = bufc + 2; if (bufs >= 3) bufs -= 3;
            issue_stage(t + 2, sb + (uint32_t)bufs * STAGEB);
        }
        cp_commit();

        {
            uint32_t base = sb + (uint32_t)bufc * STAGEB;
            uint32_t aX = base;
            uint32_t bH = base + ATILE;

            #pragma unroll
            for (int ks = 0; ks < 2; ks++) {
                uint32_t ah[4][4], bh[4][2];
                #pragma unroll
                for (int fm = 0; fm < 4; fm++)
                    ldsm4(ah[fm][0], ah[fm][1], ah[fm][2], ah[fm][3], aX + a_off[fm][ks]);
                #pragma unroll
                for (int fnp = 0; fnp < 2; fnp++) {
                    uint32_t r0, r1, r2, r3;
                    ldsm4(r0, r1, r2, r3, bH + b_off[fnp][ks]);
                    bh[fnp*2][0]=r0; bh[fnp*2][1]=r1; bh[fnp*2+1][0]=r2; bh[fnp*2+1][1]=r3;
                }
                #pragma unroll
                for (int fm = 0; fm < 4; fm++)
                    #pragma unroll
                    for (int fn = 0; fn < 4; fn++)
                        mma16816h(d[fm][fn], ah[fm][0],ah[fm][1],ah[fm][2],ah[fm][3],
                                  bh[fn][0], bh[fn][1]);
            }
        }
        bufc = (bufc + 1 == 3) ? 0 : bufc + 1;
    }

    #pragma unroll
    for (int fm = 0; fm < 4; fm++) {
        int mrow = bm + wm*64 + fm*16 + g;
        #pragma unroll
        for (int half = 0; half < 2; half++) {
            int m = mrow + half*8;
            #pragma unroll
            for (int fn = 0; fn < 4; fn++) {
                int n0 = bn + wn*32 + fn*8 + tg*2;
                float v0 = d[fm][fn][half*2+0];
                float v1 = d[fm][fn][half*2+1];
                if (bias) { v0 += bias[n0]; v1 += bias[n0+1]; }
                if (GELU) { v0 = gelu_tanh(v0); v1 = gelu_tanh(v1); }
                if (RES) {
                    float2 rv = *(const float2*)&res[(size_t)m*N + n0];
                    v0 += rv.x; v1 += rv.y;
                }
                if (OUTHALF) {
                    *(uint32_t*)&Yh[(size_t)m*N + n0] = packh2(v0, v1);
                } else {
                    float2 o2; o2.x = v0; o2.y = v1;
                    *(float2*)&Y[(size_t)m*N + n0] = o2;
                }
            }
        }
    }
}

// ---------------- tensor-core flash attention (bf16 3-term, fp16 output) ----
__global__ void __launch_bounds__(256)
attn_tc(const float* __restrict__ qkv, __half* __restrict__ yh)
{
    __shared__ char smem[32768];
    const uint32_t sb = smem_u32(smem);
    const int tid  = threadIdx.x;
    const int lane = tid & 31;
    const int w    = tid >> 5;
    const int g    = lane >> 2;
    const int tg   = lane & 3;
    const int qt   = gridDim.x - 1 - blockIdx.x;
    const int h    = blockIdx.y;
    const int b    = blockIdx.z;
    const int q0   = qt * 128;

    const float SC = 0.18033688011112042f;   // 0.125 * log2(e)

    {
        int r  = tid >> 1;
        int dh = (tid & 1) * 32;
        const float* src = qkv + (size_t)(b*TT + q0 + r)*C3 + h*DD + dh;
        #pragma unroll
        for (int cc = 0; cc < 4; cc++) {
            float4 v0 = *(const float4*)(src + cc*8);
            float4 v1 = *(const float4*)(src + cc*8 + 4);
            uint4 Hc, Lc;
            Hc.x = pack2(v0.x*SC, v0.y*SC, Lc.x);
            Hc.y = pack2(v0.z*SC, v0.w*SC, Lc.y);
            Hc.z = pack2(v1.x*SC, v1.y*SC, Lc.z);
            Hc.w = pack2(v1.z*SC, v1.w*SC, Lc.w);
            int c = (dh >> 3) + cc;
            uint32_t off = (uint32_t)(r*128 + ((c ^ (r & 7)) << 4));
            *(uint4*)(smem + off)         = Hc;
            *(uint4*)(smem + 16384 + off) = Lc;
        }
    }
    __syncthreads();

    uint32_t qh[4][4], ql[4][4];
    #pragma unroll
    for (int kk = 0; kk < 4; kk++) {
        int row = w*16 + (lane & 15);
        int c   = kk*2 + (lane >> 4);
        uint32_t off = (uint32_t)(row*128 + ((c ^ (row & 7)) << 4));
        ldsm4(qh[kk][0], qh[kk][1], qh[kk][2], qh[kk][3], sb + off);
        ldsm4(ql[kk][0], ql[kk][1], ql[kk][2], ql[kk][3], sb + 16384 + off);
    }

    float o[8][4];
    #pragma unroll
    for (int j = 0; j < 8; j++) { o[j][0]=0.f; o[j][1]=0.f; o[j][2]=0.f; o[j][3]=0.f; }
    float mrow0 = -1e30f, mrow1 = -1e30f, lrow0 = 0.f, lrow1 = 0.f;

    const int qrow0 = q0 + w*16 + g;
    const int nk  = (q0 + 128) >> 6;
    const int nkw = ((q0 + w*16 + 15) >> 6) + 1;

    const uint32_t KH_ = 0u, KL_ = 8192u, VH_ = 16384u, VL_ = 24576u;

    for (int kt = 0; kt < nk; kt++) {
        __syncthreads();

        {
            int r  = tid >> 2;
            int dq = (tid & 3) * 16;
            const float* kr = qkv + (size_t)(b*TT + kt*64 + r)*C3 + CC + h*DD + dq;
            const float* vr = kr + CC;
            #pragma unroll
            for (int half = 0; half < 2; half++) {
                int c = (dq >> 3) + half;
                uint32_t off = (uint32_t)(r*128 + ((c ^ (r & 7)) << 4));
                float4 k0 = *(const float4*)(kr + half*8);
                float4 k1 = *(const float4*)(kr + half*8 + 4);
                uint4 Hc, Lc;
                Hc.x = pack2(k0.x, k0.y, Lc.x);
                Hc.y = pack2(k0.z, k0.w, Lc.y);
                Hc.z = pack2(k1.x, k1.y, Lc.z);
                Hc.w = pack2(k1.z, k1.w, Lc.w);
                *(uint4*)(smem + KH_ + off) = Hc;
                *(uint4*)(smem + KL_ + off) = Lc;
                float4 w0 = *(const float4*)(vr + half*8);
                float4 w1 = *(const float4*)(vr + half*8 + 4);
                Hc.x = pack2(w0.x, w0.y, Lc.x);
                Hc.y = pack2(w0.z, w0.w, Lc.y);
                Hc.z = pack2(w1.x, w1.y, Lc.z);
                Hc.w = pack2(w1.z, w1.w, Lc.w);
                *(uint4*)(smem + VH_ + off) = Hc;
                *(uint4*)(smem + VL_ + off) = Lc;
            }
        }
        __syncthreads();

        if (kt >= nkw) continue;

        float s[8][4];
        #pragma unroll
        for (int j = 0; j < 8; j++) { s[j][0]=0.f; s[j][1]=0.f; s[j][2]=0.f; s[j][3]=0.f; }

        #pragma unroll
        for (int kk = 0; kk < 4; kk++) {
            int q4 = lane >> 3;
            #pragma unroll
            for (int jj = 0; jj < 4; jj++) {
                int row = jj*16 + ((q4 >> 1) << 3) + (lane & 7);
                int c   = kk*2 + (q4 & 1);
                uint32_t off = (uint32_t)(row*128 + ((c ^ (row & 7)) << 4));
                uint32_t h0,h1,h2,h3, l0,l1,l2,l3;
                ldsm4(h0, h1, h2, h3, sb + KH_ + off);
                ldsm4(l0, l1, l2, l3, sb + KL_ + off);
                mma16816(s[2*jj  ], qh[kk][0],qh[kk][1],qh[kk][2],qh[kk][3], h0, h1);
                mma16816(s[2*jj  ], ql[kk][0],ql[kk][1],ql[kk][2],ql[kk][3], h0, h1);
                mma16816(s[2*jj  ], qh[kk][0],qh[kk][1],qh[kk][2],qh[kk][3], l0, l1);
                mma16816(s[2*jj+1], qh[kk][0],qh[kk][1],qh[kk][2],qh[kk][3], h2, h3);
                mma16816(s[2*jj+1], ql[kk][0],ql[kk][1],ql[kk][2],ql[kk][3], h2, h3);
                mma16816(s[2*jj+1], qh[kk][0],qh[kk][1],qh[kk][2],qh[kk][3], l2, l3);
            }
        }

        if (kt*64 + 63 > q0 + w*16) {
            #pragma unroll
            for (int j = 0; j < 8; j++) {
                int c0 = kt*64 + j*8 + 2*tg;
                if (c0     > qrow0)     s[j][0] = -1e30f;
                if (c0 + 1 > qrow0)     s[j][1] = -1e30f;
                if (c0     > qrow0 + 8) s[j][2] = -1e30f;
                if (c0 + 1 > qrow0 + 8) s[j][3] = -1e30f;
            }
        }

        float mx0 = -1e30f, mx1 = -1e30f;
        #pragma unroll
        for (int j = 0; j < 8; j++) {
            mx0 = fmaxf(mx0, fmaxf(s[j][0], s[j][1]));
            mx1 = fmaxf(mx1, fmaxf(s[j][2], s[j][3]));
        }
        mx0 = fmaxf(mx0, __shfl_xor_sync(0xffffffffu, mx0, 1));
        mx0 = fmaxf(mx0, __shfl_xor_sync(0xffffffffu, mx0, 2));
        mx1 = fmaxf(mx1, __shfl_xor_sync(0xffffffffu, mx1, 1));
        mx1 = fmaxf(mx1, __shfl_xor_sync(0xffffffffu, mx1, 2));

        float mn0 = fmaxf(mrow0, mx0), mn1 = fmaxf(mrow1, mx1);
        float a0  = ex2f(mrow0 - mn0), a1  = ex2f(mrow1 - mn1);
        float ls0 = 0.f, ls1 = 0.f;
        #pragma unroll
        for (int j = 0; j < 8; j++) {
            s[j][0] = ex2f(s[j][0] - mn0);  ls0 += s[j][0];
            s[j][1] = ex2f(s[j][1] - mn0);  ls0 += s[j][1];
            s[j][2] = ex2f(s[j][2] - mn1);  ls1 += s[j][2];
            s[j][3] = ex2f(s[j][3] - mn1);  ls1 += s[j][3];
        }
        ls0 += __shfl_xor_sync(0xffffffffu, ls0, 1);
        ls0 += __shfl_xor_sync(0xffffffffu, ls0, 2);
        ls1 += __shfl_xor_sync(0xffffffffu, ls1, 1);
        ls1 += __shfl_xor_sync(0xffffffffu, ls1, 2);
        lrow0 = lrow0*a0 + ls0;  lrow1 = lrow1*a1 + ls1;
        mrow0 = mn0;  mrow1 = mn1;
        #pragma unroll
        for (int j = 0; j < 8; j++) {
            o[j][0] *= a0; o[j][1] *= a0; o[j][2] *= a1; o[j][3] *= a1;
        }

        uint32_t* sp = (uint32_t*)s;
        #pragma unroll
        for (int kk = 0; kk < 4; kk++) {
            uint32_t lo;
            uint32_t h0 = pack2(s[2*kk][0],   s[2*kk][1],   lo);
            sp[kk*8+0] = h0; sp[kk*8+1] = lo;
            uint32_t h1 = pack2(s[2*kk][2],   s[2*kk][3],   lo);
            sp[kk*8+2] = h1; sp[kk*8+3] = lo;
            uint32_t h2 = pack2(s[2*kk+1][0], s[2*kk+1][1], lo);
            sp[kk*8+4] = h2; sp[kk*8+5] = lo;
            uint32_t h3 = pack2(s[2*kk+1][2], s[2*kk+1][3], lo);
            sp[kk*8+6] = h3; sp[kk*8+7] = lo;
        }

        #pragma unroll
        for (int kk = 0; kk < 4; kk++) {
            uint32_t pa0 = sp[kk*8+0], pa1 = sp[kk*8+2], pa2 = sp[kk*8+4], pa3 = sp[kk*8+6];
            uint32_t pb0 = sp[kk*8+1], pb1 = sp[kk*8+3], pb2 = sp[kk*8+5], pb3 = sp[kk*8+7];
            int tl = lane >> 3;
            #pragma unroll
            for (int jj = 0; jj < 4; jj++) {
                int row = kk*16 + ((tl & 1) << 3) + (lane & 7);
                int c   = jj*2 + (tl >> 1);
                uint32_t off = (uint32_t)(row*128 + ((c ^ (row & 7)) << 4));
                uint32_t v0,v1,v2,v3, u0,u1,u2,u3;
                ldsm4t(v0, v1, v2, v3, sb + VH_ + off);
                ldsm4t(u0, u1, u2, u3, sb + VL_ + off);
                mma16816(o[2*jj  ], pa0, pa1, pa2, pa3, v0, v1);
                mma16816(o[2*jj  ], pb0, pb1, pb2, pb3, v0, v1);
                mma16816(o[2*jj  ], pa0, pa1, pa2, pa3, u0, u1);
                mma16816(o[2*jj+1], pa0, pa1, pa2, pa3, v2, v3);
                mma16816(o[2*jj+1], pb0, pb1, pb2, pb3, v2, v3);
                mma16816(o[2*jj+1], pa0, pa1, pa2, pa3, u2, u3);
            }
        }
    }

    float inv0 = 1.0f / lrow0, inv1 = 1.0f / lrow1;
    #pragma unroll
    for (int j = 0; j < 8; j++) {
        size_t oidx = (size_t)(b*TT + qrow0)*CC + h*DD + j*8 + 2*tg;
        *(uint32_t*)&yh[oidx] = packh2(o[j][0]*inv0, o[j][1]*inv0);
        oidx += (size_t)8*CC;
        *(uint32_t*)&yh[oidx] = packh2(o[j][2]*inv1, o[j][3]*inv1);
    }
}

// ---------------- launch ----------------
extern "C" void kernel_launch(void* const* d_in, const int* in_sizes, int n_in,
                              void* d_out, int out_size)
{
    (void)in_sizes; (void)n_in; (void)out_size;
    const int*   idx     = (const int*)  d_in[0];
    const float* wte     = (const float*)d_in[1];
    const float* wpe     = (const float*)d_in[2];
    const float* ln1w    = (const float*)d_in[3];
    const float* ln1b    = (const float*)d_in[4];
    const float* qkvw    = (const float*)d_in[5];
    const float* qkvb    = (const float*)d_in[6];
    const float* projw   = (const float*)d_in[7];
    const float* projb   = (const float*)d_in[8];
    const float* ln2w    = (const float*)d_in[9];
    const float* ln2b    = (const float*)d_in[10];
    const float* fcw     = (const float*)d_in[11];
    const float* fcb     = (const float*)d_in[12];
    const float* fcprojw = (const float*)d_in[13];
    const float* fcprojb = (const float*)d_in[14];
    const float* lnfw    = (const float*)d_in[15];
    const float* lnfb    = (const float*)d_in[16];
    float* out = (float*)d_out;

    float *x, *qkv;
    __half *ln, *att, *act;
    __half *qkvwh, *projwh, *fcwh, *fcpwh, *wteh;
    cudaGetSymbolAddress((void**)&x,    g_x);
    cudaGetSymbolAddress((void**)&qkv,  g_qkv);
    cudaGetSymbolAddress((void**)&ln,   g_ln);
    cudaGetSymbolAddress((void**)&att,  g_att);
    cudaGetSymbolAddress((void**)&act,  g_act);
    cudaGetSymbolAddress((void**)&qkvwh, g_qkvw_h);
    cudaGetSymbolAddress((void**)&projwh,g_projw_h);
    cudaGetSymbolAddress((void**)&fcwh, g_fcw_h);
    cudaGetSymbolAddress((void**)&fcpwh,g_fcpw_h);
    cudaGetSymbolAddress((void**)&wteh, g_wte_h);

    cudaFuncSetAttribute(gemm_hmma<false,false,false>, cudaFuncAttributeMaxDynamicSharedMemorySize, GSMEM);
    cudaFuncSetAttribute(gemm_hmma<false,true ,false>, cudaFuncAttributeMaxDynamicSharedMemorySize, GSMEM);
    cudaFuncSetAttribute(gemm_hmma<true ,false,true >, cudaFuncAttributeMaxDynamicSharedMemorySize, GSMEM);

    const int SB = 1184;
    conv_kernel<<<SB, 256>>>(qkvw,    qkvwh, (long)LL*C3*CC/4);
    conv_kernel<<<SB, 256>>>(projw,   projwh,(long)LL*CC*CC/4);
    conv_kernel<<<SB, 256>>>(fcw,     fcwh,  (long)LL*C4*CC/4);
    conv_kernel<<<SB, 256>>>(fcprojw, fcpwh, (long)LL*CC*C4/4);
    conv_kernel<<<SB, 256>>>(wte,     wteh,  (long)VP*CC/4);

    embed_kernel<<<MROWS, 256>>>(idx, wte, wpe, x);

    for (int l = 0; l < LL; l++) {
        ln_kernel<<<MROWS, 256>>>(x, ln1w + l*CC, ln1b + l*CC, ln);

        gemm_hmma<false,false,false><<<dim3(MROWS/128, C3/128), 256, GSMEM>>>(
            ln, qkvwh + (size_t)l*C3*CC,
            qkvb + (size_t)l*C3, nullptr, qkv, nullptr, MROWS, C3, CC);

        attn_tc<<<dim3(TT/128, HH, BATCH), 256>>>(qkv, att);

        gemm_hmma<false,true,false><<<dim3(MROWS/128, CC/128), 256, GSMEM>>>(
            att, projwh + (size_t)l*CC*CC,
            projb + (size_t)l*CC, x, x, nullptr, MROWS, CC, CC);

        ln_kernel<<<MROWS, 256>>>(x, ln2w + l*CC, ln2b + l*CC, ln);

        gemm_hmma<true,false,true><<<dim3(MROWS/128, C4/128), 256, GSMEM>>>(
            ln, fcwh + (size_t)l*C4*CC,
            fcb + (size_t)l*C4, nullptr, nullptr, act, MROWS, C4, CC);

        gemm_hmma<false,true,false><<<dim3(MROWS/128, CC/128), 256, GSMEM>>>(
            act, fcpwh + (size_t)l*CC*C4,
            fcprojb + (size_t)l*CC, x, x, nullptr, MROWS, CC, C4);
    }

    ln_kernel<<<MROWS, 256>>>(x, lnfw, lnfb, ln);

    gemm_hmma<false,false,false><<<dim3(MROWS/128, VP/128), 256, GSMEM>>>(
        ln, wteh, nullptr, nullptr, out, nullptr, MROWS, VP, CC);
}

// round 13
// speedup vs baseline: 1.5633x; 1.1068x over previous
#include <cuda_runtime.h>
#include <cuda_bf16.h>
#include <cuda_fp16.h>
#include <math.h>
#include <stdint.h>

// ---------------- problem constants ----------------
#define BATCH 2
#define TT    1024
#define CC    768
#define HH    12
#define DD    64
#define LL    12
#define MROWS (BATCH*TT)      // 2048
#define C3    (3*CC)          // 2304
#define C4    (4*CC)          // 3072
#define VP    50304

// ---------------- scratch (device globals) ----------
__device__ float g_x  [MROWS*CC];
__device__ float g_qkv[MROWS*C3];

__device__ __half g_ln [MROWS*CC];
__device__ __half g_att[MROWS*CC];
__device__ __half g_act[MROWS*C4];

__device__ __half g_qkvw_h [(size_t)LL*C3*CC];
__device__ __half g_projw_h[(size_t)LL*CC*CC];
__device__ __half g_fcw_h  [(size_t)LL*C4*CC];
__device__ __half g_fcpw_h [(size_t)LL*CC*C4];
__device__ __half g_wte_h  [(size_t)VP*CC];

// ---------------- small helpers ----------------
__device__ __forceinline__ uint32_t packh2(float x, float y)
{
    __half2 H; H.x = __float2half(x); H.y = __float2half(y);
    return *reinterpret_cast<const uint32_t*>(&H);
}

__device__ __forceinline__ float gelu_tanh(float x) {
    float x3 = x*x*x;
    return 0.5f * x * (1.0f + tanhf(0.7978845608028654f * (x + 0.044715f * x3)));
}

__device__ __forceinline__ float ex2f(float x) {
    float y;
    asm("ex2.approx.f32 %0, %1;" : "=f"(y) : "f"(x));
    return y;
}
// packed fp16x2 exp2: returns {lo=2^lo_in, hi=2^hi_in} as f16x2
__device__ __forceinline__ uint32_t ex2h2(float lo, float hi) {
    uint32_t r;
    asm("{\n\t.reg .b32 t;\n\t"
        "cvt.rn.f16x2.f32 t, %2, %1;\n\t"
        "ex2.approx.f16x2 %0, t;\n\t}"
        : "=r"(r) : "f"(lo), "f"(hi));
    return r;
}

__device__ __forceinline__ uint32_t smem_u32(const void* p) {
    uint32_t a;
    asm("{ .reg .u64 t; cvta.to.shared.u64 t, %1; cvt.u32.u64 %0, t; }"
        : "=r"(a) : "l"(p));
    return a;
}
__device__ __forceinline__ void cpasync16(uint32_t dst, const void* src) {
    asm volatile("cp.async.cg.shared.global [%0], [%1], 16;"
                 :: "r"(dst), "l"(__cvta_generic_to_global(src)));
}
__device__ __forceinline__ void cp_commit() {
    asm volatile("cp.async.commit_group;");
}
template<int N>
__device__ __forceinline__ void cp_wait() {
    asm volatile("cp.async.wait_group %0;" :: "n"(N));
}
__device__ __forceinline__ void ldsm4(uint32_t& r0, uint32_t& r1,
                                      uint32_t& r2, uint32_t& r3, uint32_t addr) {
    asm volatile("ldmatrix.sync.aligned.m8n8.x4.shared.b16 {%0,%1,%2,%3}, [%4];"
                 : "=r"(r0), "=r"(r1), "=r"(r2), "=r"(r3) : "r"(addr));
}
__device__ __forceinline__ void ldsm4t(uint32_t& r0, uint32_t& r1,
                                       uint32_t& r2, uint32_t& r3, uint32_t addr) {
    asm volatile("ldmatrix.sync.aligned.m8n8.x4.trans.shared.b16 {%0,%1,%2,%3}, [%4];"
                 : "=r"(r0), "=r"(r1), "=r"(r2), "=r"(r3) : "r"(addr));
}
__device__ __forceinline__ void mma16816h(float* d,
    uint32_t a0, uint32_t a1, uint32_t a2, uint32_t a3,
    uint32_t b0, uint32_t b1)
{
    asm volatile(
        "mma.sync.aligned.m16n8k16.row.col.f32.f16.f16.f32 "
        "{%0,%1,%2,%3}, {%4,%5,%6,%7}, {%8,%9}, {%0,%1,%2,%3};"
        : "+f"(d[0]), "+f"(d[1]), "+f"(d[2]), "+f"(d[3])
        : "r"(a0), "r"(a1), "r"(a2), "r"(a3), "r"(b0), "r"(b1));
}

// ---------------- weight convert fp32 -> fp16 ----------------
__global__ void conv_kernel(const float* __restrict__ s,
                            __half* __restrict__ h, long n4)
{
    long stride = (long)gridDim.x * blockDim.x;
    for (long i = (long)blockIdx.x * blockDim.x + threadIdx.x; i < n4; i += stride) {
        float4 v = ((const float4*)s)[i];
        uint2 H;
        H.x = packh2(v.x, v.y);
        H.y = packh2(v.z, v.w);
        ((uint2*)h)[i] = H;
    }
}

// ---------------- embedding ----------------
__global__ void embed_kernel(const int* __restrict__ idx,
                             const float* __restrict__ wte,
                             const float* __restrict__ wpe,
                             float* __restrict__ x)
{
    int m = blockIdx.x;
    int t = m & (TT-1);
    int tok = idx[m];
    const float* we = wte + (size_t)tok * CC;
    const float* wp = wpe + (size_t)t * CC;
    float* xr = x + (size_t)m * CC;
    for (int c = threadIdx.x; c < CC; c += blockDim.x)
        xr[c] = we[c] + wp[c];
}

// ---------------- layernorm -> fp16 ----------
__global__ void ln_kernel(const float* __restrict__ x,
                          const float* __restrict__ w,
                          const float* __restrict__ b,
                          __half* __restrict__ yh)
{
    __shared__ float red[16];
    int row  = blockIdx.x;
    int tid  = threadIdx.x;
    int lane = tid & 31;
    int warp = tid >> 5;
    const float* xr = x + (size_t)row * CC;

    float v0 = xr[tid], v1 = xr[tid+256], v2 = xr[tid+512];
    float s = v0 + v1 + v2;
    #pragma unroll
    for (int o = 16; o; o >>= 1) s += __shfl_xor_sync(0xffffffffu, s, o);
    if (!lane) red[warp] = s;
    __syncthreads();
    float mu = (red[0]+red[1]+red[2]+red[3]+red[4]+red[5]+red[6]+red[7]) * (1.0f/CC);

    float d0 = v0-mu, d1 = v1-mu, d2 = v2-mu;
    float q = d0*d0 + d1*d1 + d2*d2;
    #pragma unroll
    for (int o = 16; o; o >>= 1) q += __shfl_xor_sync(0xffffffffu, q, o);
    if (!lane) red[8+warp] = q;
    __syncthreads();
    float rstd = rsqrtf((red[8]+red[9]+red[10]+red[11]+red[12]+red[13]+red[14]+red[15])
                        * (1.0f/CC) + 1e-5f);

    size_t base = (size_t)row * CC;
    #pragma unroll
    for (int j = 0; j < 3; j++) {
        int c = tid + j*256;
        float v = (j==0?d0:(j==1?d1:d2))*rstd*w[c] + b[c];
        yh[base+c] = __float2half(v);
    }
}

// ---------------- fp16 HMMA GEMM, 128x128 tile, single-term ----------
#define BKG 32
#define ATILE  8192
#define BTILE  8192
#define STAGEB (ATILE + BTILE)     // 16KB
#define GSMEM  (3*STAGEB)          // 49152

template<bool GELU, bool RES, bool OUTHALF>
__global__ void __launch_bounds__(256)
gemm_hmma(const __half* __restrict__ X, const __half* __restrict__ Wh,
          const float* __restrict__ bias, const float* __restrict__ res,
          float* __restrict__ Y, __half* __restrict__ Yh,
          int M, int N, int K)
{
    extern __shared__ char sm[];
    const uint32_t sb = smem_u32(sm);

    const int tid  = threadIdx.x;
    const int lane = tid & 31;
    const int warp = tid >> 5;
    const int wm   = warp & 1;
    const int wn   = warp >> 1;
    const int g    = lane >> 2;
    const int tg   = lane & 3;
    const int bm   = blockIdx.x * 128;
    const int bn   = blockIdx.y * 128;

    float d[4][4][4];
    #pragma unroll
    for (int i = 0; i < 4; i++)
        #pragma unroll
        for (int j = 0; j < 4; j++) {
            d[i][j][0]=0.f; d[i][j][1]=0.f; d[i][j][2]=0.f; d[i][j][3]=0.f;
        }

    const int lr  = tid >> 1;
    const int lcb = (tid & 1) * 2;
    const __half* x_p  = X  + (size_t)(bm + lr)*K;
    const __half* wh_p = Wh + (size_t)(bn + lr)*K;
    const int rsw = (lr >> 1) & 3;
    uint32_t so[2];
    #pragma unroll
    for (int i = 0; i < 2; i++)
        so[i] = (uint32_t)(lr*64 + (((lcb+i) ^ rsw) << 4));

    uint32_t a_off[4][2], b_off[2][2];
    {
        int arow = wm*64 + (lane & 15);
        int ln16 = lane >> 4;
        #pragma unroll
        for (int fm = 0; fm < 4; fm++) {
            int r = arow + fm*16;
            #pragma unroll
            for (int ks = 0; ks < 2; ks++) {
                int c = ks*2 + ln16;
                a_off[fm][ks] = (uint32_t)(r*64 + ((c ^ ((r>>1)&3)) << 4));
            }
        }
        int q = lane >> 3;
        int brow = wn*32 + ((q >> 1) << 3) + (lane & 7);
        int cadd = q & 1;
        #pragma unroll
        for (int fnp = 0; fnp < 2; fnp++) {
            int r = brow + fnp*16;
            #pragma unroll
            for (int ks = 0; ks < 2; ks++) {
                int c = ks*2 + cadd;
                b_off[fnp][ks] = (uint32_t)(r*64 + ((c ^ ((r>>1)&3)) << 4));
            }
        }
    }

    const int NT = K / BKG;

    auto issue_stage = [&](int stage, uint32_t base) {
        const int k0 = stage * BKG;
        #pragma unroll
        for (int i = 0; i < 2; i++) {
            int c = lcb + i;
            cpasync16(base +          so[i], (const char*)(x_p  + k0) + c*16);
            cpasync16(base + ATILE +  so[i], (const char*)(wh_p + k0) + c*16);
        }
    };

    #pragma unroll
    for (int s = 0; s < 2; s++) {
        issue_stage(s, sb + (uint32_t)s * STAGEB);
        cp_commit();
    }

    int bufc = 0;
    for (int t = 0; t < NT; t++) {
        cp_wait<1>();
        __syncthreads();

        if (t + 2 < NT) {
            int bufs = bufc + 2; if (bufs >= 3) bufs -= 3;
            issue_stage(t + 2, sb + (uint32_t)bufs * STAGEB);
        }
        cp_commit();

        {
            uint32_t base = sb + (uint32_t)bufc * STAGEB;
            uint32_t aX = base;
            uint32_t bH = base + ATILE;

            #pragma unroll
            for (int ks = 0; ks < 2; ks++) {
                uint32_t ah[4][4], bh[4][2];
                #pragma unroll
                for (int fm = 0; fm < 4; fm++)
                    ldsm4(ah[fm][0], ah[fm][1], ah[fm][2], ah[fm][3], aX + a_off[fm][ks]);
                #pragma unroll
                for (int fnp = 0; fnp < 2; fnp++) {
                    uint32_t r0, r1, r2, r3;
                    ldsm4(r0, r1, r2, r3, bH + b_off[fnp][ks]);
                    bh[fnp*2][0]=r0; bh[fnp*2][1]=r1; bh[fnp*2+1][0]=r2; bh[fnp*2+1][1]=r3;
                }
                #pragma unroll
                for (int fm = 0; fm < 4; fm++)
                    #pragma unroll
                    for (int fn = 0; fn < 4; fn++)
                        mma16816h(d[fm][fn], ah[fm][0],ah[fm][1],ah[fm][2],ah[fm][3],
                                  bh[fn][0], bh[fn][1]);
            }
        }
        bufc = (bufc + 1 == 3) ? 0 : bufc + 1;
    }

    #pragma unroll
    for (int fm = 0; fm < 4; fm++) {
        int mrow = bm + wm*64 + fm*16 + g;
        #pragma unroll
        for (int half = 0; half < 2; half++) {
            int m = mrow + half*8;
            #pragma unroll
            for (int fn = 0; fn < 4; fn++) {
                int n0 = bn + wn*32 + fn*8 + tg*2;
                float v0 = d[fm][fn][half*2+0];
                float v1 = d[fm][fn][half*2+1];
                if (bias) { v0 += bias[n0]; v1 += bias[n0+1]; }
                if (GELU) { v0 = gelu_tanh(v0); v1 = gelu_tanh(v1); }
                if (RES) {
                    float2 rv = *(const float2*)&res[(size_t)m*N + n0];
                    v0 += rv.x; v1 += rv.y;
                }
                if (OUTHALF) {
                    *(uint32_t*)&Yh[(size_t)m*N + n0] = packh2(v0, v1);
                } else {
                    float2 o2; o2.x = v0; o2.y = v1;
                    *(float2*)&Y[(size_t)m*N + n0] = o2;
                }
            }
        }
    }
}

// ---------------- fp16 tensor-core flash attention ----------------
// 128 q/CTA, 64-key tiles, 8 warps x 16 q-rows. Q/K/V/P fp16 single-term,
// fp32 softmax state, exp via ex2.approx.f16x2 (2 exps per MUFU op).
// smem 16KB: Q staging [128][64]h overlaid by K[64][64]h + V[64][64]h.
__global__ void __launch_bounds__(256)
attn_tc(const float* __restrict__ qkv, __half* __restrict__ yh)
{
    __shared__ char smem[16384];
    const uint32_t sb = smem_u32(smem);
    const int tid  = threadIdx.x;
    const int lane = tid & 31;
    const int w    = tid >> 5;
    const int g    = lane >> 2;
    const int tg   = lane & 3;
    const int qt   = gridDim.x - 1 - blockIdx.x;   // heavy tiles first
    const int h    = blockIdx.y;
    const int b    = blockIdx.z;
    const int q0   = qt * 128;

    const float SC = 0.18033688011112042f;   // 0.125 * log2(e)

    // ---- stage Q (scaled fp16) ----
    {
        int r  = tid >> 1;
        int dh = (tid & 1) * 32;
        const float* src = qkv + (size_t)(b*TT + q0 + r)*C3 + h*DD + dh;
        #pragma unroll
        for (int cc = 0; cc < 4; cc++) {
            float4 v0 = *(const float4*)(src + cc*8);
            float4 v1 = *(const float4*)(src + cc*8 + 4);
            uint4 Hc;
            Hc.x = packh2(v0.x*SC, v0.y*SC);
            Hc.y = packh2(v0.z*SC, v0.w*SC);
            Hc.z = packh2(v1.x*SC, v1.y*SC);
            Hc.w = packh2(v1.z*SC, v1.w*SC);
            int c = (dh >> 3) + cc;
            uint32_t off = (uint32_t)(r*128 + ((c ^ (r & 7)) << 4));
            *(uint4*)(smem + off) = Hc;
        }
    }
    __syncthreads();

    // ---- Q fragments to registers ----
    uint32_t qf[4][4];
    #pragma unroll
    for (int kk = 0; kk < 4; kk++) {
        int row = w*16 + (lane & 15);
        int c   = kk*2 + (lane >> 4);
        uint32_t off = (uint32_t)(row*128 + ((c ^ (row & 7)) << 4));
        ldsm4(qf[kk][0], qf[kk][1], qf[kk][2], qf[kk][3], sb + off);
    }

    float o[8][4];
    #pragma unroll
    for (int j = 0; j < 8; j++) { o[j][0]=0.f; o[j][1]=0.f; o[j][2]=0.f; o[j][3]=0.f; }
    float mrow0 = -1e30f, mrow1 = -1e30f, lrow0 = 0.f, lrow1 = 0.f;

    const int qrow0 = q0 + w*16 + g;
    const int nk  = (q0 + 128) >> 6;
    const int nkw = ((q0 + w*16 + 15) >> 6) + 1;

    const uint32_t K_ = 0u, V_ = 8192u;

    for (int kt = 0; kt < nk; kt++) {
        __syncthreads();   // prev compute done (and Q frags read on kt==0)

        // ---- load K,V tile (fp16) ----
        {
            int r  = tid >> 2;
            int dq = (tid & 3) * 16;
            const float* kr = qkv + (size_t)(b*TT + kt*64 + r)*C3 + CC + h*DD + dq;
            const float* vr = kr + CC;
            #pragma unroll
            for (int half = 0; half < 2; half++) {
                int c = (dq >> 3) + half;
                uint32_t off = (uint32_t)(r*128 + ((c ^ (r & 7)) << 4));
                float4 k0 = *(const float4*)(kr + half*8);
                float4 k1 = *(const float4*)(kr + half*8 + 4);
                uint4 Hc;
                Hc.x = packh2(k0.x, k0.y); Hc.y = packh2(k0.z, k0.w);
                Hc.z = packh2(k1.x, k1.y); Hc.w = packh2(k1.z, k1.w);
                *(uint4*)(smem + K_ + off) = Hc;
                float4 w0 = *(const float4*)(vr + half*8);
                float4 w1 = *(const float4*)(vr + half*8 + 4);
                Hc.x = packh2(w0.x, w0.y); Hc.y = packh2(w0.z, w0.w);
                Hc.z = packh2(w1.x, w1.y); Hc.w = packh2(w1.z, w1.w);
                *(uint4*)(smem + V_ + off) = Hc;
            }
        }
        __syncthreads();

        if (kt >= nkw) continue;   // fully masked for this warp; barriers already hit

        // ---- S = Q K^T (fp16 single-term) ----
        float s[8][4];
        #pragma unroll
        for (int j = 0; j < 8; j++) { s[j][0]=0.f; s[j][1]=0.f; s[j][2]=0.f; s[j][3]=0.f; }

        #pragma unroll
        for (int kk = 0; kk < 4; kk++) {
            int q4 = lane >> 3;
            #pragma unroll
            for (int jj = 0; jj < 4; jj++) {
                int row = jj*16 + ((q4 >> 1) << 3) + (lane & 7);
                int c   = kk*2 + (q4 & 1);
                uint32_t off = (uint32_t)(row*128 + ((c ^ (row & 7)) << 4));
                uint32_t k0,k1,k2,k3;
                ldsm4(k0, k1, k2, k3, sb + K_ + off);
                mma16816h(s[2*jj  ], qf[kk][0],qf[kk][1],qf[kk][2],qf[kk][3], k0, k1);
                mma16816h(s[2*jj+1], qf[kk][0],qf[kk][1],qf[kk][2],qf[kk][3], k2, k3);
            }
        }

        // ---- causal mask ----
        if (kt*64 + 63 > q0 + w*16) {
            #pragma unroll
            for (int j = 0; j < 8; j++) {
                int c0 = kt*64 + j*8 + 2*tg;
                if (c0     > qrow0)     s[j][0] = -1e30f;
                if (c0 + 1 > qrow0)     s[j][1] = -1e30f;
                if (c0     > qrow0 + 8) s[j][2] = -1e30f;
                if (c0 + 1 > qrow0 + 8) s[j][3] = -1e30f;
            }
        }

        // ---- online softmax (log2 domain), packed fp16 exp ----
        float mx0 = -1e30f, mx1 = -1e30f;
        #pragma unroll
        for (int j = 0; j < 8; j++) {
            mx0 = fmaxf(mx0, fmaxf(s[j][0], s[j][1]));
            mx1 = fmaxf(mx1, fmaxf(s[j][2], s[j][3]));
        }
        mx0 = fmaxf(mx0, __shfl_xor_sync(0xffffffffu, mx0, 1));
        mx0 = fmaxf(mx0, __shfl_xor_sync(0xffffffffu, mx0, 2));
        mx1 = fmaxf(mx1, __shfl_xor_sync(0xffffffffu, mx1, 1));
        mx1 = fmaxf(mx1, __shfl_xor_sync(0xffffffffu, mx1, 2));

        float mn0 = fmaxf(mrow0, mx0), mn1 = fmaxf(mrow1, mx1);
        float a0  = ex2f(mrow0 - mn0), a1  = ex2f(mrow1 - mn1);

        uint32_t p[8][2];
        float ls0 = 0.f, ls1 = 0.f;
        #pragma unroll
        for (int j = 0; j < 8; j++) {
            p[j][0] = ex2h2(s[j][0] - mn0, s[j][1] - mn0);
            p[j][1] = ex2h2(s[j][2] - mn1, s[j][3] - mn1);
            float2 f0 = __half22float2(*reinterpret_cast<const __half2*>(&p[j][0]));
            float2 f1 = __half22float2(*reinterpret_cast<const __half2*>(&p[j][1]));
            ls0 += f0.x + f0.y;
            ls1 += f1.x + f1.y;
        }
        ls0 += __shfl_xor_sync(0xffffffffu, ls0, 1);
        ls0 += __shfl_xor_sync(0xffffffffu, ls0, 2);
        ls1 += __shfl_xor_sync(0xffffffffu, ls1, 1);
        ls1 += __shfl_xor_sync(0xffffffffu, ls1, 2);
        lrow0 = lrow0*a0 + ls0;  lrow1 = lrow1*a1 + ls1;
        mrow0 = mn0;  mrow1 = mn1;
        #pragma unroll
        for (int j = 0; j < 8; j++) {
            o[j][0] *= a0; o[j][1] *= a0; o[j][2] *= a1; o[j][3] *= a1;
        }

        // ---- O += P V (fp16 single-term; p[] regs are A-fragments already) ----
        #pragma unroll
        for (int kk = 0; kk < 4; kk++) {
            uint32_t pa0 = p[2*kk  ][0], pa1 = p[2*kk  ][1];
            uint32_t pa2 = p[2*kk+1][0], pa3 = p[2*kk+1][1];
            int tl = lane >> 3;
            #pragma unroll
            for (int jj = 0; jj < 4; jj++) {
                int row = kk*16 + ((tl & 1) << 3) + (lane & 7);
                int c   = jj*2 + (tl >> 1);
                uint32_t off = (uint32_t)(row*128 + ((c ^ (row & 7)) << 4));
                uint32_t v0,v1,v2,v3;
                ldsm4t(v0, v1, v2, v3, sb + V_ + off);
                mma16816h(o[2*jj  ], pa0, pa1, pa2, pa3, v0, v1);
                mma16816h(o[2*jj+1], pa0, pa1, pa2, pa3, v2, v3);
            }
        }
    }

    // ---- epilogue ----
    float inv0 = 1.0f / lrow0, inv1 = 1.0f / lrow1;
    #pragma unroll
    for (int j = 0; j < 8; j++) {
        size_t oidx = (size_t)(b*TT + qrow0)*CC + h*DD + j*8 + 2*tg;
        *(uint32_t*)&yh[oidx] = packh2(o[j][0]*inv0, o[j][1]*inv0);
        oidx += (size_t)8*CC;
        *(uint32_t*)&yh[oidx] = packh2(o[j][2]*inv1, o[j][3]*inv1);
    }
}

// ---------------- launch ----------------
extern "C" void kernel_launch(void* const* d_in, const int* in_sizes, int n_in,
                              void* d_out, int out_size)
{
    (void)in_sizes; (void)n_in; (void)out_size;
    const int*   idx     = (const int*)  d_in[0];
    const float* wte     = (const float*)d_in[1];
    const float* wpe     = (const float*)d_in[2];
    const float* ln1w    = (const float*)d_in[3];
    const float* ln1b    = (const float*)d_in[4];
    const float* qkvw    = (const float*)d_in[5];
    const float* qkvb    = (const float*)d_in[6];
    const float* projw   = (const float*)d_in[7];
    const float* projb   = (const float*)d_in[8];
    const float* ln2w    = (const float*)d_in[9];
    const float* ln2b    = (const float*)d_in[10];
    const float* fcw     = (const float*)d_in[11];
    const float* fcb     = (const float*)d_in[12];
    const float* fcprojw = (const float*)d_in[13];
    const float* fcprojb = (const float*)d_in[14];
    const float* lnfw    = (const float*)d_in[15];
    const float* lnfb    = (const float*)d_in[16];
    float* out = (float*)d_out;

    float *x, *qkv;
    __half *ln, *att, *act;
    __half *qkvwh, *projwh, *fcwh, *fcpwh, *wteh;
    cudaGetSymbolAddress((void**)&x,    g_x);
    cudaGetSymbolAddress((void**)&qkv,  g_qkv);
    cudaGetSymbolAddress((void**)&ln,   g_ln);
    cudaGetSymbolAddress((void**)&att,  g_att);
    cudaGetSymbolAddress((void**)&act,  g_act);
    cudaGetSymbolAddress((void**)&qkvwh, g_qkvw_h);
    cudaGetSymbolAddress((void**)&projwh,g_projw_h);
    cudaGetSymbolAddress((void**)&fcwh, g_fcw_h);
    cudaGetSymbolAddress((void**)&fcpwh,g_fcpw_h);
    cudaGetSymbolAddress((void**)&wteh, g_wte_h);

    cudaFuncSetAttribute(gemm_hmma<false,false,false>, cudaFuncAttributeMaxDynamicSharedMemorySize, GSMEM);
    cudaFuncSetAttribute(gemm_hmma<false,true ,false>, cudaFuncAttributeMaxDynamicSharedMemorySize, GSMEM);
    cudaFuncSetAttribute(gemm_hmma<true ,false,true >, cudaFuncAttributeMaxDynamicSharedMemorySize, GSMEM);

    const int SB = 1184;
    conv_kernel<<<SB, 256>>>(qkvw,    qkvwh, (long)LL*C3*CC/4);
    conv_kernel<<<SB, 256>>>(projw,   projwh,(long)LL*CC*CC/4);
    conv_kernel<<<SB, 256>>>(fcw,     fcwh,  (long)LL*C4*CC/4);
    conv_kernel<<<SB, 256>>>(fcprojw, fcpwh, (long)LL*CC*C4/4);
    conv_kernel<<<SB, 256>>>(wte,     wteh,  (long)VP*CC/4);

    embed_kernel<<<MROWS, 256>>>(idx, wte, wpe, x);

    for (int l = 0; l < LL; l++) {
        ln_kernel<<<MROWS, 256>>>(x, ln1w + l*CC, ln1b + l*CC, ln);

        gemm_hmma<false,false,false><<<dim3(MROWS/128, C3/128), 256, GSMEM>>>(
            ln, qkvwh + (size_t)l*C3*CC,
            qkvb + (size_t)l*C3, nullptr, qkv, nullptr, MROWS, C3, CC);

        attn_tc<<<dim3(TT/128, HH, BATCH), 256>>>(qkv, att);

        gemm_hmma<false,true,false><<<dim3(MROWS/128, CC/128), 256, GSMEM>>>(
            att, projwh + (size_t)l*CC*CC,
            projb + (size_t)l*CC, x, x, nullptr, MROWS, CC, CC);

        ln_kernel<<<MROWS, 256>>>(x, ln2w + l*CC, ln2b + l*CC, ln);

        gemm_hmma<true,false,true><<<dim3(MROWS/128, C4/128), 256, GSMEM>>>(
            ln, fcwh + (size_t)l*C4*CC,
            fcb + (size_t)l*C4, nullptr, nullptr, act, MROWS, C4, CC);

        gemm_hmma<false,true,false><<<dim3(MROWS/128, CC/128), 256, GSMEM>>>(
            act, fcpwh + (size_t)l*CC*C4,
            fcprojb + (size_t)l*CC, x, x, nullptr, MROWS, CC, C4);
    }

    ln_kernel<<<MROWS, 256>>>(x, lnfw, lnfb, ln);

    gemm_hmma<false,false,false><<<dim3(MROWS/128, VP/128), 256, GSMEM>>>(
        ln, wteh, nullptr, nullptr, out, nullptr, MROWS, VP, CC);
}

// round 14
// speedup vs baseline: 1.6358x; 1.0464x over previous
#include <cuda_runtime.h>
#include <cuda_bf16.h>
#include <cuda_fp16.h>
#include <math.h>
#include <stdint.h>

// ---------------- problem constants ----------------
#define BATCH 2
#define TT    1024
#define CC    768
#define HH    12
#define DD    64
#define LL    12
#define MROWS (BATCH*TT)      // 2048
#define C3    (3*CC)          // 2304
#define C4    (4*CC)          // 3072
#define VP    50304

// ---------------- scratch (device globals) ----------
__device__ float  g_x   [MROWS*CC];
__device__ __half g_qkvh[MROWS*C3];

__device__ __half g_ln [MROWS*CC];
__device__ __half g_att[MROWS*CC];
__device__ __half g_act[MROWS*C4];

__device__ __half g_qkvw_h [(size_t)LL*C3*CC];
__device__ __half g_projw_h[(size_t)LL*CC*CC];
__device__ __half g_fcw_h  [(size_t)LL*C4*CC];
__device__ __half g_fcpw_h [(size_t)LL*CC*C4];
__device__ __half g_wte_h  [(size_t)VP*CC];

// ---------------- small helpers ----------------
__device__ __forceinline__ uint32_t packh2(float x, float y)
{
    __half2 H; H.x = __float2half(x); H.y = __float2half(y);
    return *reinterpret_cast<const uint32_t*>(&H);
}

__device__ __forceinline__ float gelu_tanh(float x) {
    float x3 = x*x*x;
    return 0.5f * x * (1.0f + tanhf(0.7978845608028654f * (x + 0.044715f * x3)));
}

__device__ __forceinline__ float ex2f(float x) {
    float y;
    asm("ex2.approx.f32 %0, %1;" : "=f"(y) : "f"(x));
    return y;
}
// packed fp16x2 exp2
__device__ __forceinline__ uint32_t ex2h2(float lo, float hi) {
    uint32_t r;
    asm("{\n\t.reg .b32 t;\n\t"
        "cvt.rn.f16x2.f32 t, %2, %1;\n\t"
        "ex2.approx.f16x2 %0, t;\n\t}"
        : "=r"(r) : "f"(lo), "f"(hi));
    return r;
}

__device__ __forceinline__ uint32_t smem_u32(const void* p) {
    uint32_t a;
    asm("{ .reg .u64 t; cvta.to.shared.u64 t, %1; cvt.u32.u64 %0, t; }"
        : "=r"(a) : "l"(p));
    return a;
}
__device__ __forceinline__ void cpasync16(uint32_t dst, const void* src) {
    asm volatile("cp.async.cg.shared.global [%0], [%1], 16;"
                 :: "r"(dst), "l"(__cvta_generic_to_global(src)));
}
__device__ __forceinline__ void cp_commit() {
    asm volatile("cp.async.commit_group;");
}
template<int N>
__device__ __forceinline__ void cp_wait() {
    asm volatile("cp.async.wait_group %0;" :: "n"(N));
}
__device__ __forceinline__ void ldsm4(uint32_t& r0, uint32_t& r1,
                                      uint32_t& r2, uint32_t& r3, uint32_t addr) {
    asm volatile("ldmatrix.sync.aligned.m8n8.x4.shared.b16 {%0,%1,%2,%3}, [%4];"
                 : "=r"(r0), "=r"(r1), "=r"(r2), "=r"(r3) : "r"(addr));
}
__device__ __forceinline__ void ldsm4t(uint32_t& r0, uint32_t& r1,
                                       uint32_t& r2, uint32_t& r3, uint32_t addr) {
    asm volatile("ldmatrix.sync.aligned.m8n8.x4.trans.shared.b16 {%0,%1,%2,%3}, [%4];"
                 : "=r"(r0), "=r"(r1), "=r"(r2), "=r"(r3) : "r"(addr));
}
__device__ __forceinline__ void mma16816h(float* d,
    uint32_t a0, uint32_t a1, uint32_t a2, uint32_t a3,
    uint32_t b0, uint32_t b1)
{
    asm volatile(
        "mma.sync.aligned.m16n8k16.row.col.f32.f16.f16.f32 "
        "{%0,%1,%2,%3}, {%4,%5,%6,%7}, {%8,%9}, {%0,%1,%2,%3};"
        : "+f"(d[0]), "+f"(d[1]), "+f"(d[2]), "+f"(d[3])
        : "r"(a0), "r"(a1), "r"(a2), "r"(a3), "r"(b0), "r"(b1));
}

// ---------------- weight convert fp32 -> fp16 ----------------
__global__ void conv_kernel(const float* __restrict__ s,
                            __half* __restrict__ h, long n4)
{
    long stride = (long)gridDim.x * blockDim.x;
    for (long i = (long)blockIdx.x * blockDim.x + threadIdx.x; i < n4; i += stride) {
        float4 v = ((const float4*)s)[i];
        uint2 H;
        H.x = packh2(v.x, v.y);
        H.y = packh2(v.z, v.w);
        ((uint2*)h)[i] = H;
    }
}

// ---------------- embedding ----------------
__global__ void embed_kernel(const int* __restrict__ idx,
                             const float* __restrict__ wte,
                             const float* __restrict__ wpe,
                             float* __restrict__ x)
{
    int m = blockIdx.x;
    int t = m & (TT-1);
    int tok = idx[m];
    const float* we = wte + (size_t)tok * CC;
    const float* wp = wpe + (size_t)t * CC;
    float* xr = x + (size_t)m * CC;
    for (int c = threadIdx.x; c < CC; c += blockDim.x)
        xr[c] = we[c] + wp[c];
}

// ---------------- layernorm -> fp16 ----------
__global__ void ln_kernel(const float* __restrict__ x,
                          const float* __restrict__ w,
                          const float* __restrict__ b,
                          __half* __restrict__ yh)
{
    __shared__ float red[16];
    int row  = blockIdx.x;
    int tid  = threadIdx.x;
    int lane = tid & 31;
    int warp = tid >> 5;
    const float* xr = x + (size_t)row * CC;

    float v0 = xr[tid], v1 = xr[tid+256], v2 = xr[tid+512];
    float s = v0 + v1 + v2;
    #pragma unroll
    for (int o = 16; o; o >>= 1) s += __shfl_xor_sync(0xffffffffu, s, o);
    if (!lane) red[warp] = s;
    __syncthreads();
    float mu = (red[0]+red[1]+red[2]+red[3]+red[4]+red[5]+red[6]+red[7]) * (1.0f/CC);

    float d0 = v0-mu, d1 = v1-mu, d2 = v2-mu;
    float q = d0*d0 + d1*d1 + d2*d2;
    #pragma unroll
    for (int o = 16; o; o >>= 1) q += __shfl_xor_sync(0xffffffffu, q, o);
    if (!lane) red[8+warp] = q;
    __syncthreads();
    float rstd = rsqrtf((red[8]+red[9]+red[10]+red[11]+red[12]+red[13]+red[14]+red[15])
                        * (1.0f/CC) + 1e-5f);

    size_t base = (size_t)row * CC;
    #pragma unroll
    for (int j = 0; j < 3; j++) {
        int c = tid + j*256;
        float v = (j==0?d0:(j==1?d1:d2))*rstd*w[c] + b[c];
        yh[base+c] = __float2half(v);
    }
}

// ---------------- fp16 HMMA GEMM, 128x128 tile, BK=64 ----------
// Y = X @ W^T (+bias)(gelu)(+res). X, W fp16.
// 8 warps (2x4); warp tile 64x32. 3-stage cp.async pipeline.
// smem tile: [128 rows][128B], chunk swizzle c ^= (r&7). Stage 32KB x3 = 96KB.
#define BKG 64
#define GTILE  16384
#define STAGEB (2*GTILE)
#define GSMEM  (3*STAGEB)     // 98304

template<bool GELU, bool RES, bool OUTHALF>
__global__ void __launch_bounds__(256)
gemm_hmma(const __half* __restrict__ X, const __half* __restrict__ Wh,
          const float* __restrict__ bias, const float* __restrict__ res,
          float* __restrict__ Y, __half* __restrict__ Yh,
          int M, int N, int K)
{
    extern __shared__ char sm[];
    const uint32_t sb = smem_u32(sm);

    const int tid  = threadIdx.x;
    const int lane = tid & 31;
    const int warp = tid >> 5;
    const int wm   = warp & 1;
    const int wn   = warp >> 1;
    const int g    = lane >> 2;
    const int tg   = lane & 3;
    const int bm   = blockIdx.x * 128;
    const int bn   = blockIdx.y * 128;

    float d[4][4][4];
    #pragma unroll
    for (int i = 0; i < 4; i++)
        #pragma unroll
        for (int j = 0; j < 4; j++) {
            d[i][j][0]=0.f; d[i][j][1]=0.f; d[i][j][2]=0.f; d[i][j][3]=0.f;
        }

    // ---- global->smem: thread covers row lr, chunks cb..cb+3 (16B each) ----
    const int lr = tid >> 1;
    const int cb = (tid & 1) * 4;
    const __half* x_p  = X  + (size_t)(bm + lr)*K;
    const __half* wh_p = Wh + (size_t)(bn + lr)*K;
    uint32_t so[4];
    #pragma unroll
    for (int i = 0; i < 4; i++)
        so[i] = (uint32_t)(lr*128 + (((cb+i) ^ (lr & 7)) << 4));

    // ---- ldmatrix fragment addresses ----
    uint32_t a_off[4][4], b_off[2][4];
    {
        int arow = wm*64 + (lane & 15);
        int ln16 = lane >> 4;
        #pragma unroll
        for (int fm = 0; fm < 4; fm++) {
            int r = arow + fm*16;
            #pragma unroll
            for (int ks = 0; ks < 4; ks++) {
                int c = ks*2 + ln16;
                a_off[fm][ks] = (uint32_t)(r*128 + ((c ^ (r & 7)) << 4));
            }
        }
        int q = lane >> 3;
        int brow = wn*32 + ((q >> 1) << 3) + (lane & 7);
        int cadd = q & 1;
        #pragma unroll
        for (int fnp = 0; fnp < 2; fnp++) {
            int r = brow + fnp*16;
            #pragma unroll
            for (int ks = 0; ks < 4; ks++) {
                int c = ks*2 + cadd;
                b_off[fnp][ks] = (uint32_t)(r*128 + ((c ^ (r & 7)) << 4));
            }
        }
    }

    const int NT = K / BKG;

    auto issue_stage = [&](int stage, uint32_t base) {
        const int k0 = stage * BKG;
        #pragma unroll
        for (int i = 0; i < 4; i++) {
            int c = cb + i;
            cpasync16(base +          so[i], (const char*)(x_p  + k0) + c*16);
            cpasync16(base + GTILE +  so[i], (const char*)(wh_p + k0) + c*16);
        }
    };

    #pragma unroll
    for (int s = 0; s < 2; s++) {
        issue_stage(s, sb + (uint32_t)s * STAGEB);
        cp_commit();
    }

    int bufc = 0;
    for (int t = 0; t < NT; t++) {
        cp_wait<1>();
        __syncthreads();

        if (t + 2 < NT) {
            int bufs = bufc + 2; if (bufs >= 3) bufs -= 3;
            issue_stage(t + 2, sb + (uint32_t)bufs * STAGEB);
        }
        cp_commit();

        {
            uint32_t base = sb + (uint32_t)bufc * STAGEB;
            uint32_t aX = base;
            uint32_t bH = base + GTILE;

            #pragma unroll
            for (int ks = 0; ks < 4; ks++) {
                uint32_t ah[4][4], bh[4][2];
                #pragma unroll
                for (int fm = 0; fm < 4; fm++)
                    ldsm4(ah[fm][0], ah[fm][1], ah[fm][2], ah[fm][3], aX + a_off[fm][ks]);
                #pragma unroll
                for (int fnp = 0; fnp < 2; fnp++) {
                    uint32_t r0, r1, r2, r3;
                    ldsm4(r0, r1, r2, r3, bH + b_off[fnp][ks]);
                    bh[fnp*2][0]=r0; bh[fnp*2][1]=r1; bh[fnp*2+1][0]=r2; bh[fnp*2+1][1]=r3;
                }
                #pragma unroll
                for (int fm = 0; fm < 4; fm++)
                    #pragma unroll
                    for (int fn = 0; fn < 4; fn++)
                        mma16816h(d[fm][fn], ah[fm][0],ah[fm][1],ah[fm][2],ah[fm][3],
                                  bh[fn][0], bh[fn][1]);
            }
        }
        bufc = (bufc + 1 == 3) ? 0 : bufc + 1;
    }

    #pragma unroll
    for (int fm = 0; fm < 4; fm++) {
        int mrow = bm + wm*64 + fm*16 + g;
        #pragma unroll
        for (int half = 0; half < 2; half++) {
            int m = mrow + half*8;
            #pragma unroll
            for (int fn = 0; fn < 4; fn++) {
                int n0 = bn + wn*32 + fn*8 + tg*2;
                float v0 = d[fm][fn][half*2+0];
                float v1 = d[fm][fn][half*2+1];
                if (bias) { v0 += bias[n0]; v1 += bias[n0+1]; }
                if (GELU) { v0 = gelu_tanh(v0); v1 = gelu_tanh(v1); }
                if (RES) {
                    float2 rv = *(const float2*)&res[(size_t)m*N + n0];
                    v0 += rv.x; v1 += rv.y;
                }
                if (OUTHALF) {
                    *(uint32_t*)&Yh[(size_t)m*N + n0] = packh2(v0, v1);
                } else {
                    float2 o2; o2.x = v0; o2.y = v1;
                    *(float2*)&Y[(size_t)m*N + n0] = o2;
                }
            }
        }
    }
}

// ---------------- fp16 flash attention, cp.async staging, double-buffered KV --
// qkv now fp16. Q unscaled in fragments; 1/8*log2e folded into softmax.
// smem 32KB: two 16KB K+V buffers; Q staged in buffer 0 then released.
__global__ void __launch_bounds__(256)
attn_tc(const __half* __restrict__ qkvh, __half* __restrict__ yh)
{
    __shared__ char smem[32768];
    const uint32_t sb = smem_u32(smem);
    const int tid  = threadIdx.x;
    const int lane = tid & 31;
    const int w    = tid >> 5;
    const int g    = lane >> 2;
    const int tg   = lane & 3;
    const int qt   = gridDim.x - 1 - blockIdx.x;
    const int h    = blockIdx.y;
    const int b    = blockIdx.z;
    const int q0   = qt * 128;

    const float SC = 0.18033688011112042f;   // 0.125 * log2(e)

    // ---- stage Q via cp.async (buffer 0) ----
    {
        int r  = tid >> 1;
        int cbq = (tid & 1) * 4;
        const char* src = (const char*)(qkvh + (size_t)(b*TT + q0 + r)*C3 + h*DD);
        #pragma unroll
        for (int i = 0; i < 4; i++) {
            int c = cbq + i;
            cpasync16(sb + (uint32_t)(r*128 + ((c ^ (r & 7)) << 4)), src + c*16);
        }
        cp_commit();
    }
    cp_wait<0>();
    __syncthreads();

    uint32_t qf[4][4];
    #pragma unroll
    for (int kk = 0; kk < 4; kk++) {
        int row = w*16 + (lane & 15);
        int c   = kk*2 + (lane >> 4);
        uint32_t off = (uint32_t)(row*128 + ((c ^ (row & 7)) << 4));
        ldsm4(qf[kk][0], qf[kk][1], qf[kk][2], qf[kk][3], sb + off);
    }
    __syncthreads();   // Q reads done before tile0 overwrites buffer 0

    // K/V staging mapping: 1024 chunks (K 512 + V 512), 4 per thread
    const int kvsel = tid >> 7;            // 0 = K, 1 = V
    const int kr    = (tid >> 1) & 63;
    const int kcb   = (tid & 1) * 4;
    uint32_t kvso[4];
    #pragma unroll
    for (int i = 0; i < 4; i++)
        kvso[i] = (uint32_t)(kvsel*8192 + kr*128 + (((kcb+i) ^ (kr & 7)) << 4));

    auto issue_kv = [&](int kt, uint32_t bufb) {
        const char* src = (const char*)(qkvh + (size_t)(b*TT + kt*64 + kr)*C3
                                        + CC + kvsel*CC + h*DD);
        #pragma unroll
        for (int i = 0; i < 4; i++)
            cpasync16(sb + bufb + kvso[i], src + (kcb+i)*16);
        cp_commit();
    };

    float o[8][4];
    #pragma unroll
    for (int j = 0; j < 8; j++) { o[j][0]=0.f; o[j][1]=0.f; o[j][2]=0.f; o[j][3]=0.f; }
    float mrow0 = -1e30f, mrow1 = -1e30f, lrow0 = 0.f, lrow1 = 0.f;

    const int qrow0 = q0 + w*16 + g;
    const int nk  = (q0 + 128) >> 6;
    const int nkw = ((q0 + w*16 + 15) >> 6) + 1;

    issue_kv(0, 0u);   // prologue: tile 0 into buffer 0

    for (int kt = 0; kt < nk; kt++) {
        cp_wait<0>();      // tile kt landed (this thread)
        __syncthreads();   // all threads' copies visible; prev compute done

        if (kt + 1 < nk)
            issue_kv(kt + 1, (uint32_t)((kt+1) & 1) * 16384);  // overlaps compute

        if (kt >= nkw) continue;

        const uint32_t K_ = (uint32_t)(kt & 1) * 16384;
        const uint32_t V_ = K_ + 8192;

        // ---- S = Q K^T ----
        float s[8][4];
        #pragma unroll
        for (int j = 0; j < 8; j++) { s[j][0]=0.f; s[j][1]=0.f; s[j][2]=0.f; s[j][3]=0.f; }

        #pragma unroll
        for (int kk = 0; kk < 4; kk++) {
            int q4 = lane >> 3;
            #pragma unroll
            for (int jj = 0; jj < 4; jj++) {
                int row = jj*16 + ((q4 >> 1) << 3) + (lane & 7);
                int c   = kk*2 + (q4 & 1);
                uint32_t off = (uint32_t)(row*128 + ((c ^ (row & 7)) << 4));
                uint32_t k0,k1,k2,k3;
                ldsm4(k0, k1, k2, k3, sb + K_ + off);
                mma16816h(s[2*jj  ], qf[kk][0],qf[kk][1],qf[kk][2],qf[kk][3], k0, k1);
                mma16816h(s[2*jj+1], qf[kk][0],qf[kk][1],qf[kk][2],qf[kk][3], k2, k3);
            }
        }

        // ---- causal mask ----
        if (kt*64 + 63 > q0 + w*16) {
            #pragma unroll
            for (int j = 0; j < 8; j++) {
                int c0 = kt*64 + j*8 + 2*tg;
                if (c0     > qrow0)     s[j][0] = -1e30f;
                if (c0 + 1 > qrow0)     s[j][1] = -1e30f;
                if (c0     > qrow0 + 8) s[j][2] = -1e30f;
                if (c0 + 1 > qrow0 + 8) s[j][3] = -1e30f;
            }
        }

        // ---- online softmax (raw logits; scale folded here) ----
        float mx0 = -1e30f, mx1 = -1e30f;
        #pragma unroll
        for (int j = 0; j < 8; j++) {
            mx0 = fmaxf(mx0, fmaxf(s[j][0], s[j][1]));
            mx1 = fmaxf(mx1, fmaxf(s[j][2], s[j][3]));
        }
        mx0 = fmaxf(mx0, __shfl_xor_sync(0xffffffffu, mx0, 1));
        mx0 = fmaxf(mx0, __shfl_xor_sync(0xffffffffu, mx0, 2));
        mx1 = fmaxf(mx1, __shfl_xor_sync(0xffffffffu, mx1, 1));
        mx1 = fmaxf(mx1, __shfl_xor_sync(0xffffffffu, mx1, 2));

        float mn0 = fmaxf(mrow0, mx0), mn1 = fmaxf(mrow1, mx1);
        float a0  = ex2f((mrow0 - mn0)*SC), a1 = ex2f((mrow1 - mn1)*SC);

        uint32_t p[8][2];
        float ls0 = 0.f, ls1 = 0.f;
        #pragma unroll
        for (int j = 0; j < 8; j++) {
            p[j][0] = ex2h2((s[j][0] - mn0)*SC, (s[j][1] - mn0)*SC);
            p[j][1] = ex2h2((s[j][2] - mn1)*SC, (s[j][3] - mn1)*SC);
            float2 f0 = __half22float2(*reinterpret_cast<const __half2*>(&p[j][0]));
            float2 f1 = __half22float2(*reinterpret_cast<const __half2*>(&p[j][1]));
            ls0 += f0.x + f0.y;
            ls1 += f1.x + f1.y;
        }
        ls0 += __shfl_xor_sync(0xffffffffu, ls0, 1);
        ls0 += __shfl_xor_sync(0xffffffffu, ls0, 2);
        ls1 += __shfl_xor_sync(0xffffffffu, ls1, 1);
        ls1 += __shfl_xor_sync(0xffffffffu, ls1, 2);
        lrow0 = lrow0*a0 + ls0;  lrow1 = lrow1*a1 + ls1;
        mrow0 = mn0;  mrow1 = mn1;
        #pragma unroll
        for (int j = 0; j < 8; j++) {
            o[j][0] *= a0; o[j][1] *= a0; o[j][2] *= a1; o[j][3] *= a1;
        }

        // ---- O += P V ----
        #pragma unroll
        for (int kk = 0; kk < 4; kk++) {
            uint32_t pa0 = p[2*kk  ][0], pa1 = p[2*kk  ][1];
            uint32_t pa2 = p[2*kk+1][0], pa3 = p[2*kk+1][1];
            int tl = lane >> 3;
            #pragma unroll
            for (int jj = 0; jj < 4; jj++) {
                int row = kk*16 + ((tl & 1) << 3) + (lane & 7);
                int c   = jj*2 + (tl >> 1);
                uint32_t off = (uint32_t)(row*128 + ((c ^ (row & 7)) << 4));
                uint32_t v0,v1,v2,v3;
                ldsm4t(v0, v1, v2, v3, sb + V_ + off);
                mma16816h(o[2*jj  ], pa0, pa1, pa2, pa3, v0, v1);
                mma16816h(o[2*jj+1], pa0, pa1, pa2, pa3, v2, v3);
            }
        }
    }

    float inv0 = 1.0f / lrow0, inv1 = 1.0f / lrow1;
    #pragma unroll
    for (int j = 0; j < 8; j++) {
        size_t oidx = (size_t)(b*TT + qrow0)*CC + h*DD + j*8 + 2*tg;
        *(uint32_t*)&yh[oidx] = packh2(o[j][0]*inv0, o[j][1]*inv0);
        oidx += (size_t)8*CC;
        *(uint32_t*)&yh[oidx] = packh2(o[j][2]*inv1, o[j][3]*inv1);
    }
}

// ---------------- launch ----------------
extern "C" void kernel_launch(void* const* d_in, const int* in_sizes, int n_in,
                              void* d_out, int out_size)
{
    (void)in_sizes; (void)n_in; (void)out_size;
    const int*   idx     = (const int*)  d_in[0];
    const float* wte     = (const float*)d_in[1];
    const float* wpe     = (const float*)d_in[2];
    const float* ln1w    = (const float*)d_in[3];
    const float* ln1b    = (const float*)d_in[4];
    const float* qkvw    = (const float*)d_in[5];
    const float* qkvb    = (const float*)d_in[6];
    const float* projw   = (const float*)d_in[7];
    const float* projb   = (const float*)d_in[8];
    const float* ln2w    = (const float*)d_in[9];
    const float* ln2b    = (const float*)d_in[10];
    const float* fcw     = (const float*)d_in[11];
    const float* fcb     = (const float*)d_in[12];
    const float* fcprojw = (const float*)d_in[13];
    const float* fcprojb = (const float*)d_in[14];
    const float* lnfw    = (const float*)d_in[15];
    const float* lnfb    = (const float*)d_in[16];
    float* out = (float*)d_out;

    float *x;
    __half *qkvh, *ln, *att, *act;
    __half *qkvwh, *projwh, *fcwh, *fcpwh, *wteh;
    cudaGetSymbolAddress((void**)&x,    g_x);
    cudaGetSymbolAddress((void**)&qkvh, g_qkvh);
    cudaGetSymbolAddress((void**)&ln,   g_ln);
    cudaGetSymbolAddress((void**)&att,  g_att);
    cudaGetSymbolAddress((void**)&act,  g_act);
    cudaGetSymbolAddress((void**)&qkvwh, g_qkvw_h);
    cudaGetSymbolAddress((void**)&projwh,g_projw_h);
    cudaGetSymbolAddress((void**)&fcwh, g_fcw_h);
    cudaGetSymbolAddress((void**)&fcpwh,g_fcpw_h);
    cudaGetSymbolAddress((void**)&wteh, g_wte_h);

    cudaFuncSetAttribute(gemm_hmma<false,false,true >, cudaFuncAttributeMaxDynamicSharedMemorySize, GSMEM);
    cudaFuncSetAttribute(gemm_hmma<false,true ,false>, cudaFuncAttributeMaxDynamicSharedMemorySize, GSMEM);
    cudaFuncSetAttribute(gemm_hmma<true ,false,true >, cudaFuncAttributeMaxDynamicSharedMemorySize, GSMEM);
    cudaFuncSetAttribute(gemm_hmma<false,false,false>, cudaFuncAttributeMaxDynamicSharedMemorySize, GSMEM);

    const int SB = 1184;
    conv_kernel<<<SB, 256>>>(qkvw,    qkvwh, (long)LL*C3*CC/4);
    conv_kernel<<<SB, 256>>>(projw,   projwh,(long)LL*CC*CC/4);
    conv_kernel<<<SB, 256>>>(fcw,     fcwh,  (long)LL*C4*CC/4);
    conv_kernel<<<SB, 256>>>(fcprojw, fcpwh, (long)LL*CC*C4/4);
    conv_kernel<<<SB, 256>>>(wte,     wteh,  (long)VP*CC/4);

    embed_kernel<<<MROWS, 256>>>(idx, wte, wpe, x);

    for (int l = 0; l < LL; l++) {
        ln_kernel<<<MROWS, 256>>>(x, ln1w + l*CC, ln1b + l*CC, ln);

        gemm_hmma<false,false,true><<<dim3(MROWS/128, C3/128), 256, GSMEM>>>(
            ln, qkvwh + (size_t)l*C3*CC,
            qkvb + (size_t)l*C3, nullptr, nullptr, qkvh, MROWS, C3, CC);

        attn_tc<<<dim3(TT/128, HH, BATCH), 256>>>(qkvh, att);

        gemm_hmma<false,true,false><<<dim3(MROWS/128, CC/128), 256, GSMEM>>>(
            att, projwh + (size_t)l*CC*CC,
            projb + (size_t)l*CC, x, x, nullptr, MROWS, CC, CC);

        ln_kernel<<<MROWS, 256>>>(x, ln2w + l*CC, ln2b + l*CC, ln);

        gemm_hmma<true,false,true><<<dim3(MROWS/128, C4/128), 256, GSMEM>>>(
            ln, fcwh + (size_t)l*C4*CC,
            fcb + (size_t)l*C4, nullptr, nullptr, act, MROWS, C4, CC);

        gemm_hmma<false,true,false><<<dim3(MROWS/128, CC/128), 256, GSMEM>>>(
            act, fcpwh + (size_t)l*CC*C4,
            fcprojb + (size_t)l*CC, x, x, nullptr, MROWS, CC, C4);
    }

    ln_kernel<<<MROWS, 256>>>(x, lnfw, lnfb, ln);

    gemm_hmma<false,false,false><<<dim3(MROWS/128, VP/128), 256, GSMEM>>>(
        ln, wteh, nullptr, nullptr, out, nullptr, MROWS, VP, CC);
}